// round 2
// baseline (speedup 1.0000x reference)
#include <cuda_runtime.h>
#include <math.h>

#define BATCH   4
#define CCH     128
#define HH      14
#define WW      14
#define SP      (HH*WW)        // 196
#define NPIX    (BATCH*SP)     // 784
#define NPROTO  2000
#define NCLS    200
#define IMG     224
#define UPF4    (IMG/4)        // 56
#define UPSZ    (IMG*IMG)      // 50176

typedef unsigned long long ull;

// packed f32x2 helpers (sm_103a FFMA2 — only via PTX)
#define PACK2(d, lo, hi)  asm("mov.b64 %0, {%1, %2};" : "=l"(d) : "f"(lo), "f"(hi))
#define UNPACK2(lo, hi, s) asm("mov.b64 {%0, %1}, %2;" : "=f"(lo), "=f"(hi) : "l"(s))
#define FMA2(acc, a, b)   asm("fma.rn.f32x2 %0, %1, %2, %3;" : "=l"(acc) : "l"(a), "l"(b), "l"(acc))

// ---------------- scratch ----------------
__device__ __align__(16) float g_f[NPIX*CCH];
__device__ __align__(16) float g_f2[NPIX];
__device__ __align__(16) float g_p2[NPROTO];
__device__ __align__(16) float g_dist[BATCH*NPROTO*SP];
__device__ __align__(16) float g_acts[BATCH*NPROTO];

// ---------------- kernel 1: addon (4 px/block) + p2 merged ----------------
__global__ void prep_kernel(const float* __restrict__ fmap,
                            const float* __restrict__ w1, const float* __restrict__ b1,
                            const float* __restrict__ w2, const float* __restrict__ b2,
                            const float* __restrict__ protos) {
    const int t = threadIdx.x;   // 128
    if (blockIdx.x >= NPIX/4) {
        // ---- ||p||^2: 4 protos per block, 32 lanes each ----
        int p = (blockIdx.x - NPIX/4) * 4 + (t >> 5);
        int lane = t & 31;
        if (p >= NPROTO) return;
        float s = 0.0f;
        #pragma unroll
        for (int c = lane; c < CCH; c += 32) {
            float v = protos[p*CCH + c];
            s = fmaf(v, v, s);
        }
        #pragma unroll
        for (int o = 16; o > 0; o >>= 1) s += __shfl_xor_sync(0xFFFFFFFFu, s, o);
        if (lane == 0) g_p2[p] = s;
        return;
    }

    const int pix0 = blockIdx.x * 4;
    __shared__ float2 xsA[CCH], xsB[CCH];
    __shared__ float2 hsA[CCH], hsB[CCH];
    __shared__ float part2[4][4];

    {
        float x[4];
        #pragma unroll
        for (int px = 0; px < 4; px++) {
            int pix = pix0 + px;
            int b = pix / SP, s = pix % SP;
            x[px] = fmap[(b*CCH + t)*SP + s];
        }
        xsA[t] = make_float2(x[0], x[1]);
        xsB[t] = make_float2(x[2], x[3]);
    }
    __syncthreads();

    ull accA, accB;
    {
        float bias = b1[t];
        PACK2(accA, bias, bias); accB = accA;
        const float* wrow = &w1[t*CCH];
        #pragma unroll 4
        for (int c = 0; c < CCH; c++) {
            float wv = wrow[c];
            ull wp; PACK2(wp, wv, wv);
            FMA2(accA, wp, *(const ull*)&xsA[c]);
            FMA2(accB, wp, *(const ull*)&xsB[c]);
        }
    }
    {
        float a0,a1,a2,a3;
        UNPACK2(a0,a1,accA); UNPACK2(a2,a3,accB);
        hsA[t] = make_float2(fmaxf(a0,0.f), fmaxf(a1,0.f));
        hsB[t] = make_float2(fmaxf(a2,0.f), fmaxf(a3,0.f));
    }
    __syncthreads();

    {
        float bias = b2[t];
        PACK2(accA, bias, bias); accB = accA;
        const float* wrow = &w2[t*CCH];
        #pragma unroll 4
        for (int c = 0; c < CCH; c++) {
            float wv = wrow[c];
            ull wp; PACK2(wp, wv, wv);
            FMA2(accA, wp, *(const ull*)&hsA[c]);
            FMA2(accB, wp, *(const ull*)&hsB[c]);
        }
    }

    float fv[4];
    {
        float a0,a1,a2,a3;
        UNPACK2(a0,a1,accA); UNPACK2(a2,a3,accB);
        fv[0] = 1.0f/(1.0f + __expf(-a0));
        fv[1] = 1.0f/(1.0f + __expf(-a1));
        fv[2] = 1.0f/(1.0f + __expf(-a2));
        fv[3] = 1.0f/(1.0f + __expf(-a3));
    }
    #pragma unroll
    for (int px = 0; px < 4; px++) g_f[(pix0+px)*CCH + t] = fv[px];

    // ||f||^2 per pixel via warp shuffles
    float v0 = fv[0]*fv[0], v1 = fv[1]*fv[1], v2 = fv[2]*fv[2], v3 = fv[3]*fv[3];
    #pragma unroll
    for (int o = 16; o > 0; o >>= 1) {
        v0 += __shfl_xor_sync(0xFFFFFFFFu, v0, o);
        v1 += __shfl_xor_sync(0xFFFFFFFFu, v1, o);
        v2 += __shfl_xor_sync(0xFFFFFFFFu, v2, o);
        v3 += __shfl_xor_sync(0xFFFFFFFFu, v3, o);
    }
    if ((t & 31) == 0) {
        int w = t >> 5;
        part2[w][0] = v0; part2[w][1] = v1; part2[w][2] = v2; part2[w][3] = v3;
    }
    __syncthreads();
    if (t < 4)
        g_f2[pix0 + t] = part2[0][t] + part2[1][t] + part2[2][t] + part2[3][t];
}

// ---------------- kernel 2: distance GEMM (f32x2) + sqrt epilogue ----------------
#define BM 64
#define BN 64
#define BK 32
#define ASTR (2*BM + 4)   // 132 floats: keeps 16B alignment, rotates banks per k-row
__global__ void dist_kernel(const float* __restrict__ protos) {
    __shared__ float As2[BK][ASTR];     // A duplicated: [a,a] pairs
    __shared__ float Bs[BK][BN + 4];
    const int tid = threadIdx.x;        // 256
    const int tx = tid & 15, ty = tid >> 4;
    const int m0 = blockIdx.y * BM;
    const int n0 = blockIdx.x * BN;

    ull acc[4][2];
    #pragma unroll
    for (int i = 0; i < 4; i++) { acc[i][0] = 0ull; acc[i][1] = 0ull; }

    for (int k0 = 0; k0 < CCH; k0 += BK) {
        #pragma unroll
        for (int l = 0; l < 2; l++) {
            int idx = tid + l*256;
            int row = idx >> 3;
            int kc4 = idx & 7;
            float4 v = make_float4(0,0,0,0);
            int m = m0 + row;
            if (m < NPIX) v = *(const float4*)&g_f[m*CCH + k0 + kc4*4];
            As2[kc4*4+0][2*row] = v.x; As2[kc4*4+0][2*row+1] = v.x;
            As2[kc4*4+1][2*row] = v.y; As2[kc4*4+1][2*row+1] = v.y;
            As2[kc4*4+2][2*row] = v.z; As2[kc4*4+2][2*row+1] = v.z;
            As2[kc4*4+3][2*row] = v.w; As2[kc4*4+3][2*row+1] = v.w;
            float4 u = make_float4(0,0,0,0);
            int n = n0 + row;
            if (n < NPROTO) u = *(const float4*)&protos[n*CCH + k0 + kc4*4];
            Bs[kc4*4+0][row] = u.x; Bs[kc4*4+1][row] = u.y;
            Bs[kc4*4+2][row] = u.z; Bs[kc4*4+3][row] = u.w;
        }
        __syncthreads();
        #pragma unroll
        for (int k = 0; k < BK; k++) {
            ulonglong2 a01 = *(const ulonglong2*)&As2[k][ty*8];      // (a0,a0),(a1,a1)
            ulonglong2 a23 = *(const ulonglong2*)&As2[k][ty*8+4];    // (a2,a2),(a3,a3)
            ulonglong2 bp  = *(const ulonglong2*)&Bs[k][tx*4];       // (b0,b1),(b2,b3)
            FMA2(acc[0][0], a01.x, bp.x); FMA2(acc[0][1], a01.x, bp.y);
            FMA2(acc[1][0], a01.y, bp.x); FMA2(acc[1][1], a01.y, bp.y);
            FMA2(acc[2][0], a23.x, bp.x); FMA2(acc[2][1], a23.x, bp.y);
            FMA2(acc[3][0], a23.y, bp.x); FMA2(acc[3][1], a23.y, bp.y);
        }
        __syncthreads();
    }

    #pragma unroll
    for (int i = 0; i < 4; i++) {
        int m = m0 + ty*4 + i;
        if (m >= NPIX) continue;
        int b = m / SP, s = m % SP;
        float f2 = g_f2[m];
        float c0,c1,c2,c3;
        UNPACK2(c0, c1, acc[i][0]);
        UNPACK2(c2, c3, acc[i][1]);
        float cr[4] = {c0, c1, c2, c3};
        #pragma unroll
        for (int j = 0; j < 4; j++) {
            int n = n0 + tx*4 + j;
            if (n >= NPROTO) continue;
            float d2 = f2 + g_p2[n] - 2.0f*cr[j];
            d2 = fmaxf(d2, 0.0f);
            g_dist[(b*NPROTO + n)*SP + s] = sqrtf(d2 + 1e-12f);
        }
    }
}

// ---------------- kernel 3: bilinear x16 upsample + min + act ----------------
__device__ __forceinline__ void bil_coef(int o, int lim, int& ia, int& ib, float& w) {
    int r = o & 15, q = o >> 4;
    int i0;
    if (r >= 8) { i0 = q;     w = (float)(r - 8) * 0.0625f + 0.03125f; }
    else        { i0 = q - 1; w = (float)(r + 8) * 0.0625f + 0.03125f; }
    ia = i0 < 0 ? 0 : i0;
    ib = (i0 + 1 > lim) ? lim : i0 + 1;
}

__global__ void upsample_kernel(float* __restrict__ up, float* __restrict__ out_min) {
    const int bp = blockIdx.x;
    const int t = threadIdx.x;                 // 256
    __shared__ float src[SP];
    __shared__ __align__(16) float hrow[HH][IMG];
    __shared__ int   iT0[IMG], iT1[IMG];
    __shared__ float wT[IMG];
    __shared__ float redw[8];

    if (t < IMG) {
        int a, b; float w;
        bil_coef(t, HH - 1, a, b, w);
        iT0[t] = a; iT1[t] = b; wT[t] = w;
    }
    if (t < SP) src[t] = g_dist[bp*SP + t];
    __syncthreads();

    // horizontal interpolation: 14 rows x 224
    for (int i = t; i < HH*IMG; i += 256) {
        int row = i / IMG, x = i - row*IMG;
        float w = wT[x];
        hrow[row][x] = (1.0f - w)*src[row*WW + iT0[x]] + w*src[row*WW + iT1[x]];
    }
    __syncthreads();

    float mn = INFINITY;
    float* dst = up + (size_t)bp * UPSZ;
    #pragma unroll 2
    for (int v = t; v < IMG*UPF4; v += 256) {
        int y = v / UPF4, xv = (v - y*UPF4) * 4;
        float w = wT[y];
        const float* ra = &hrow[iT0[y]][xv];
        const float* rb = &hrow[iT1[y]][xv];
        float4 A = *(const float4*)ra;
        float4 B = *(const float4*)rb;
        float wi = 1.0f - w;
        float4 o;
        o.x = wi*A.x + w*B.x;
        o.y = wi*A.y + w*B.y;
        o.z = wi*A.z + w*B.z;
        o.w = wi*A.w + w*B.w;
        mn = fminf(mn, fminf(fminf(o.x, o.y), fminf(o.z, o.w)));
        __stcs((float4*)&dst[(size_t)v*4], o);
    }

    #pragma unroll
    for (int o = 16; o > 0; o >>= 1) mn = fminf(mn, __shfl_xor_sync(0xFFFFFFFFu, mn, o));
    if ((t & 31) == 0) redw[t >> 5] = mn;
    __syncthreads();
    if (t == 0) {
        float m = redw[0];
        #pragma unroll
        for (int w = 1; w < 8; w++) m = fminf(m, redw[w]);
        out_min[bp] = m;
        g_acts[bp] = __logf((m + 1.0f) / (m + 1e-4f));
    }
}

// ---------------- kernel 4: logits ----------------
__global__ void logits_kernel(const float* __restrict__ last_w, float* __restrict__ out) {
    const int cls = blockIdx.x;
    const int b = blockIdx.y;
    const int t = threadIdx.x;        // 256
    __shared__ float red[8];
    const float* a = &g_acts[b*NPROTO];
    const float* wr = &last_w[cls*NPROTO];
    float s = 0.0f;
    for (int p = t; p < NPROTO; p += 256) s = fmaf(a[p], wr[p], s);
    #pragma unroll
    for (int o = 16; o > 0; o >>= 1) s += __shfl_xor_sync(0xFFFFFFFFu, s, o);
    if ((t & 31) == 0) red[t >> 5] = s;
    __syncthreads();
    if (t == 0) {
        float tot = 0.0f;
        #pragma unroll
        for (int w = 0; w < 8; w++) tot += red[w];
        out[b*NCLS + cls] = tot;
    }
}

// ---------------- launch ----------------
extern "C" void kernel_launch(void* const* d_in, const int* in_sizes, int n_in,
                              void* d_out, int out_size) {
    const float* fmap   = (const float*)d_in[0];
    const float* w1     = (const float*)d_in[1];
    const float* b1     = (const float*)d_in[2];
    const float* w2     = (const float*)d_in[3];
    const float* b2     = (const float*)d_in[4];
    const float* protos = (const float*)d_in[5];
    const float* last_w = (const float*)d_in[6];

    float* out        = (float*)d_out;
    float* out_logits = out;                               // 4*200
    float* out_min    = out + BATCH*NCLS;                  // 4*2000
    float* out_up     = out + BATCH*NCLS + BATCH*NPROTO;   // 4*2000*224*224

    const int addon_blocks = NPIX/4;                       // 196
    const int p2_blocks = (NPROTO + 3)/4;                  // 500
    prep_kernel<<<addon_blocks + p2_blocks, CCH>>>(fmap, w1, b1, w2, b2, protos);
    dist_kernel<<<dim3((NPROTO + BN - 1)/BN, (NPIX + BM - 1)/BM), 256>>>(protos);
    upsample_kernel<<<BATCH*NPROTO, 256>>>(out_up, out_min);
    logits_kernel<<<dim3(NCLS, BATCH), 256>>>(last_w, out_logits);
}

// round 3
// speedup vs baseline: 1.4867x; 1.4867x over previous
#include <cuda_runtime.h>
#include <math.h>

#define BATCH   4
#define CCH     128
#define HH      14
#define WW      14
#define SP      (HH*WW)        // 196
#define NPIX    (BATCH*SP)     // 784
#define NPROTO  2000
#define NCLS    200
#define IMG     224
#define UPF4    (IMG/4)        // 56
#define UPSZ    (IMG*IMG)      // 50176

typedef unsigned long long ull;

// packed f32x2 helpers (sm_103a FFMA2 — only via PTX)
#define PACK2(d, lo, hi)  asm("mov.b64 %0, {%1, %2};" : "=l"(d) : "f"(lo), "f"(hi))
#define UNPACK2(lo, hi, s) asm("mov.b64 {%0, %1}, %2;" : "=f"(lo), "=f"(hi) : "l"(s))
#define FMA2(acc, a, b)   asm("fma.rn.f32x2 %0, %1, %2, %3;" : "=l"(acc) : "l"(a), "l"(b), "l"(acc))

// ---------------- scratch ----------------
__device__ __align__(16) float g_f[NPIX*CCH];
__device__ __align__(16) float g_f2[NPIX];
__device__ __align__(16) float g_p2[NPROTO];
__device__ __align__(16) float g_dist[BATCH*NPROTO*SP];
__device__ __align__(16) float g_acts[BATCH*NPROTO];

// ---------------- kernel 1: addon (4 px/block) + p2 merged ----------------
__global__ void prep_kernel(const float* __restrict__ fmap,
                            const float* __restrict__ w1, const float* __restrict__ b1,
                            const float* __restrict__ w2, const float* __restrict__ b2,
                            const float* __restrict__ protos) {
    const int t = threadIdx.x;   // 128
    if (blockIdx.x >= NPIX/4) {
        // ---- ||p||^2: 4 protos per block, 32 lanes each ----
        int p = (blockIdx.x - NPIX/4) * 4 + (t >> 5);
        int lane = t & 31;
        if (p >= NPROTO) return;
        float s = 0.0f;
        #pragma unroll
        for (int c = lane; c < CCH; c += 32) {
            float v = protos[p*CCH + c];
            s = fmaf(v, v, s);
        }
        #pragma unroll
        for (int o = 16; o > 0; o >>= 1) s += __shfl_xor_sync(0xFFFFFFFFu, s, o);
        if (lane == 0) g_p2[p] = s;
        return;
    }

    const int pix0 = blockIdx.x * 4;
    __shared__ float2 xsA[CCH], xsB[CCH];
    __shared__ float2 hsA[CCH], hsB[CCH];
    __shared__ float part2[4][4];

    {
        float x[4];
        #pragma unroll
        for (int px = 0; px < 4; px++) {
            int pix = pix0 + px;
            int b = pix / SP, s = pix % SP;
            x[px] = fmap[(b*CCH + t)*SP + s];
        }
        xsA[t] = make_float2(x[0], x[1]);
        xsB[t] = make_float2(x[2], x[3]);
    }
    __syncthreads();

    ull accA, accB;
    {
        float bias = b1[t];
        PACK2(accA, bias, bias); accB = accA;
        const float* wrow = &w1[t*CCH];
        #pragma unroll 4
        for (int c = 0; c < CCH; c++) {
            float wv = wrow[c];
            ull wp; PACK2(wp, wv, wv);
            FMA2(accA, wp, *(const ull*)&xsA[c]);
            FMA2(accB, wp, *(const ull*)&xsB[c]);
        }
    }
    {
        float a0,a1,a2,a3;
        UNPACK2(a0,a1,accA); UNPACK2(a2,a3,accB);
        hsA[t] = make_float2(fmaxf(a0,0.f), fmaxf(a1,0.f));
        hsB[t] = make_float2(fmaxf(a2,0.f), fmaxf(a3,0.f));
    }
    __syncthreads();

    {
        float bias = b2[t];
        PACK2(accA, bias, bias); accB = accA;
        const float* wrow = &w2[t*CCH];
        #pragma unroll 4
        for (int c = 0; c < CCH; c++) {
            float wv = wrow[c];
            ull wp; PACK2(wp, wv, wv);
            FMA2(accA, wp, *(const ull*)&hsA[c]);
            FMA2(accB, wp, *(const ull*)&hsB[c]);
        }
    }

    float fv[4];
    {
        float a0,a1,a2,a3;
        UNPACK2(a0,a1,accA); UNPACK2(a2,a3,accB);
        fv[0] = 1.0f/(1.0f + __expf(-a0));
        fv[1] = 1.0f/(1.0f + __expf(-a1));
        fv[2] = 1.0f/(1.0f + __expf(-a2));
        fv[3] = 1.0f/(1.0f + __expf(-a3));
    }
    #pragma unroll
    for (int px = 0; px < 4; px++) g_f[(pix0+px)*CCH + t] = fv[px];

    // ||f||^2 per pixel via warp shuffles
    float v0 = fv[0]*fv[0], v1 = fv[1]*fv[1], v2 = fv[2]*fv[2], v3 = fv[3]*fv[3];
    #pragma unroll
    for (int o = 16; o > 0; o >>= 1) {
        v0 += __shfl_xor_sync(0xFFFFFFFFu, v0, o);
        v1 += __shfl_xor_sync(0xFFFFFFFFu, v1, o);
        v2 += __shfl_xor_sync(0xFFFFFFFFu, v2, o);
        v3 += __shfl_xor_sync(0xFFFFFFFFu, v3, o);
    }
    if ((t & 31) == 0) {
        int w = t >> 5;
        part2[w][0] = v0; part2[w][1] = v1; part2[w][2] = v2; part2[w][3] = v3;
    }
    __syncthreads();
    if (t < 4)
        g_f2[pix0 + t] = part2[0][t] + part2[1][t] + part2[2][t] + part2[3][t];
}

// ---------------- kernel 2: distance GEMM (f32x2) + sqrt epilogue ----------------
#define BM 64
#define BN 64
#define BK 32
#define ASTR (2*BM + 4)
__global__ void dist_kernel(const float* __restrict__ protos) {
    __shared__ float As2[BK][ASTR];     // A duplicated: [a,a] pairs
    __shared__ float Bs[BK][BN + 4];
    const int tid = threadIdx.x;        // 256
    const int tx = tid & 15, ty = tid >> 4;
    const int m0 = blockIdx.y * BM;
    const int n0 = blockIdx.x * BN;

    ull acc[4][2];
    #pragma unroll
    for (int i = 0; i < 4; i++) { acc[i][0] = 0ull; acc[i][1] = 0ull; }

    for (int k0 = 0; k0 < CCH; k0 += BK) {
        #pragma unroll
        for (int l = 0; l < 2; l++) {
            int idx = tid + l*256;
            int row = idx >> 3;
            int kc4 = idx & 7;
            float4 v = make_float4(0,0,0,0);
            int m = m0 + row;
            if (m < NPIX) v = *(const float4*)&g_f[m*CCH + k0 + kc4*4];
            As2[kc4*4+0][2*row] = v.x; As2[kc4*4+0][2*row+1] = v.x;
            As2[kc4*4+1][2*row] = v.y; As2[kc4*4+1][2*row+1] = v.y;
            As2[kc4*4+2][2*row] = v.z; As2[kc4*4+2][2*row+1] = v.z;
            As2[kc4*4+3][2*row] = v.w; As2[kc4*4+3][2*row+1] = v.w;
            float4 u = make_float4(0,0,0,0);
            int n = n0 + row;
            if (n < NPROTO) u = *(const float4*)&protos[n*CCH + k0 + kc4*4];
            Bs[kc4*4+0][row] = u.x; Bs[kc4*4+1][row] = u.y;
            Bs[kc4*4+2][row] = u.z; Bs[kc4*4+3][row] = u.w;
        }
        __syncthreads();
        #pragma unroll
        for (int k = 0; k < BK; k++) {
            ulonglong2 a01 = *(const ulonglong2*)&As2[k][ty*8];
            ulonglong2 a23 = *(const ulonglong2*)&As2[k][ty*8+4];
            ulonglong2 bp  = *(const ulonglong2*)&Bs[k][tx*4];
            FMA2(acc[0][0], a01.x, bp.x); FMA2(acc[0][1], a01.x, bp.y);
            FMA2(acc[1][0], a01.y, bp.x); FMA2(acc[1][1], a01.y, bp.y);
            FMA2(acc[2][0], a23.x, bp.x); FMA2(acc[2][1], a23.x, bp.y);
            FMA2(acc[3][0], a23.y, bp.x); FMA2(acc[3][1], a23.y, bp.y);
        }
        __syncthreads();
    }

    #pragma unroll
    for (int i = 0; i < 4; i++) {
        int m = m0 + ty*4 + i;
        if (m >= NPIX) continue;
        int b = m / SP, s = m % SP;
        float f2 = g_f2[m];
        float c0,c1,c2,c3;
        UNPACK2(c0, c1, acc[i][0]);
        UNPACK2(c2, c3, acc[i][1]);
        float cr[4] = {c0, c1, c2, c3};
        #pragma unroll
        for (int j = 0; j < 4; j++) {
            int n = n0 + tx*4 + j;
            if (n >= NPROTO) continue;
            float d2 = f2 + g_p2[n] - 2.0f*cr[j];
            d2 = fmaxf(d2, 0.0f);
            g_dist[(b*NPROTO + n)*SP + s] = sqrtf(d2 + 1e-12f);
        }
    }
}

// ---------------- kernel 3: bilinear x16 upsample (R1 proven version) ----------------
__device__ __forceinline__ void bil_coef(int o, int lim, int& ia, int& ib, float& w) {
    int r = o & 15, q = o >> 4;
    int i0;
    if (r >= 8) { i0 = q;     w = (float)(r - 8) * 0.0625f + 0.03125f; }
    else        { i0 = q - 1; w = (float)(r + 8) * 0.0625f + 0.03125f; }
    ia = i0 < 0 ? 0 : i0;
    ib = (i0 + 1 > lim) ? lim : i0 + 1;
}

__global__ void upsample_kernel(float* __restrict__ up, float* __restrict__ out_min) {
    const int bp = blockIdx.x;                 // b*NPROTO + p
    const int t = threadIdx.x;                 // 256
    __shared__ float src[SP];
    __shared__ __align__(16) float hrow[HH][IMG];   // 12.25 KB
    __shared__ float red[256];

    if (t < SP) src[t] = g_dist[bp*SP + t];
    __syncthreads();

    // horizontal interpolation: 14 rows x 224
    for (int i = t; i < HH*IMG; i += 256) {
        int row = i / IMG, x = i - row*IMG;
        int xa, xb; float w;
        bil_coef(x, WW - 1, xa, xb, w);
        hrow[row][x] = (1.0f - w)*src[row*WW + xa] + w*src[row*WW + xb];
    }
    __syncthreads();

    float mn = INFINITY;
    float* dst = up + (size_t)bp * UPSZ;
    // 224 rows x 56 float4 = 12544 float4, contiguous in v
    for (int v = t; v < IMG*UPF4; v += 256) {
        int y = v / UPF4, xv = (v - y*UPF4) * 4;
        int ya, yb; float w;
        bil_coef(y, HH - 1, ya, yb, w);
        float4 A = *(const float4*)&hrow[ya][xv];
        float4 B = *(const float4*)&hrow[yb][xv];
        float4 o;
        float wi = 1.0f - w;
        o.x = wi*A.x + w*B.x;
        o.y = wi*A.y + w*B.y;
        o.z = wi*A.z + w*B.z;
        o.w = wi*A.w + w*B.w;
        mn = fminf(mn, fminf(fminf(o.x, o.y), fminf(o.z, o.w)));
        __stcs((float4*)&dst[(size_t)v*4], o);
    }

    red[t] = mn;
    __syncthreads();
    #pragma unroll
    for (int off = 128; off > 0; off >>= 1) {
        if (t < off) red[t] = fminf(red[t], red[t + off]);
        __syncthreads();
    }
    if (t == 0) {
        float m = red[0];
        out_min[bp] = m;
        g_acts[bp] = logf((m + 1.0f) / (m + 1e-4f));
    }
}

// ---------------- kernel 4: logits ----------------
__global__ void logits_kernel(const float* __restrict__ last_w, float* __restrict__ out) {
    const int cls = blockIdx.x;
    const int b = blockIdx.y;
    const int t = threadIdx.x;        // 256
    __shared__ float red[8];
    const float* a = &g_acts[b*NPROTO];
    const float* wr = &last_w[cls*NPROTO];
    float s = 0.0f;
    for (int p = t; p < NPROTO; p += 256) s = fmaf(a[p], wr[p], s);
    #pragma unroll
    for (int o = 16; o > 0; o >>= 1) s += __shfl_xor_sync(0xFFFFFFFFu, s, o);
    if ((t & 31) == 0) red[t >> 5] = s;
    __syncthreads();
    if (t == 0) {
        float tot = 0.0f;
        #pragma unroll
        for (int w = 0; w < 8; w++) tot += red[w];
        out[b*NCLS + cls] = tot;
    }
}

// ---------------- launch ----------------
extern "C" void kernel_launch(void* const* d_in, const int* in_sizes, int n_in,
                              void* d_out, int out_size) {
    const float* fmap   = (const float*)d_in[0];
    const float* w1     = (const float*)d_in[1];
    const float* b1     = (const float*)d_in[2];
    const float* w2     = (const float*)d_in[3];
    const float* b2     = (const float*)d_in[4];
    const float* protos = (const float*)d_in[5];
    const float* last_w = (const float*)d_in[6];

    float* out        = (float*)d_out;
    float* out_logits = out;                               // 4*200
    float* out_min    = out + BATCH*NCLS;                  // 4*2000
    float* out_up     = out + BATCH*NCLS + BATCH*NPROTO;   // 4*2000*224*224

    const int addon_blocks = NPIX/4;                       // 196
    const int p2_blocks = (NPROTO + 3)/4;                  // 500
    prep_kernel<<<addon_blocks + p2_blocks, CCH>>>(fmap, w1, b1, w2, b2, protos);
    dist_kernel<<<dim3((NPROTO + BN - 1)/BN, (NPIX + BM - 1)/BM), 256>>>(protos);
    upsample_kernel<<<BATCH*NPROTO, 256>>>(out_up, out_min);
    logits_kernel<<<dim3(NCLS, BATCH), 256>>>(last_w, out_logits);
}

// round 4
// speedup vs baseline: 1.4986x; 1.0080x over previous
#include <cuda_runtime.h>
#include <math.h>

#define BATCH   4
#define CCH     128
#define HH      14
#define WW      14
#define SP      (HH*WW)        // 196
#define NPIX    (BATCH*SP)     // 784
#define NPROTO  2000
#define NCLS    200
#define IMG     224
#define UPF4    (IMG/4)        // 56
#define UPSZ    (IMG*IMG)      // 50176

typedef unsigned long long ull;

// packed f32x2 helpers (sm_103a FFMA2 — only via PTX)
#define PACK2(d, lo, hi)  asm("mov.b64 %0, {%1, %2};" : "=l"(d) : "f"(lo), "f"(hi))
#define UNPACK2(lo, hi, s) asm("mov.b64 {%0, %1}, %2;" : "=f"(lo), "=f"(hi) : "l"(s))
#define FMA2(acc, a, b)   asm("fma.rn.f32x2 %0, %1, %2, %3;" : "=l"(acc) : "l"(a), "l"(b), "l"(acc))

// ---------------- scratch ----------------
__device__ __align__(16) float g_f[NPIX*CCH];
__device__ __align__(16) float g_f2[NPIX];
__device__ __align__(16) float g_p2[NPROTO];
__device__ __align__(16) float g_dist[BATCH*NPROTO*SP];

// ---------------- kernel 1: addon (4 px/block) + p2 merged + logits zero ----------------
__global__ void prep_kernel(const float* __restrict__ fmap,
                            const float* __restrict__ w1, const float* __restrict__ b1,
                            const float* __restrict__ w2, const float* __restrict__ b2,
                            const float* __restrict__ protos,
                            float* __restrict__ out_logits) {
    const int t = threadIdx.x;   // 128
    if (blockIdx.x == 0) {
        // zero the logits accumulator (d_out is poisoned to 0xAA)
        #pragma unroll
        for (int i = t; i < BATCH*NCLS; i += CCH) out_logits[i] = 0.0f;
    }
    if (blockIdx.x >= NPIX/4) {
        // ---- ||p||^2: 4 protos per block, 32 lanes each ----
        int p = (blockIdx.x - NPIX/4) * 4 + (t >> 5);
        int lane = t & 31;
        if (p >= NPROTO) return;
        float s = 0.0f;
        #pragma unroll
        for (int c = lane; c < CCH; c += 32) {
            float v = protos[p*CCH + c];
            s = fmaf(v, v, s);
        }
        #pragma unroll
        for (int o = 16; o > 0; o >>= 1) s += __shfl_xor_sync(0xFFFFFFFFu, s, o);
        if (lane == 0) g_p2[p] = s;
        return;
    }

    const int pix0 = blockIdx.x * 4;
    __shared__ float2 xsA[CCH], xsB[CCH];
    __shared__ float2 hsA[CCH], hsB[CCH];
    __shared__ float part2[4][4];

    {
        float x[4];
        #pragma unroll
        for (int px = 0; px < 4; px++) {
            int pix = pix0 + px;
            int b = pix / SP, s = pix % SP;
            x[px] = fmap[(b*CCH + t)*SP + s];
        }
        xsA[t] = make_float2(x[0], x[1]);
        xsB[t] = make_float2(x[2], x[3]);
    }
    __syncthreads();

    ull accA, accB;
    {
        float bias = b1[t];
        PACK2(accA, bias, bias); accB = accA;
        const float* wrow = &w1[t*CCH];
        #pragma unroll 4
        for (int c = 0; c < CCH; c++) {
            float wv = wrow[c];
            ull wp; PACK2(wp, wv, wv);
            FMA2(accA, wp, *(const ull*)&xsA[c]);
            FMA2(accB, wp, *(const ull*)&xsB[c]);
        }
    }
    {
        float a0,a1,a2,a3;
        UNPACK2(a0,a1,accA); UNPACK2(a2,a3,accB);
        hsA[t] = make_float2(fmaxf(a0,0.f), fmaxf(a1,0.f));
        hsB[t] = make_float2(fmaxf(a2,0.f), fmaxf(a3,0.f));
    }
    __syncthreads();

    {
        float bias = b2[t];
        PACK2(accA, bias, bias); accB = accA;
        const float* wrow = &w2[t*CCH];
        #pragma unroll 4
        for (int c = 0; c < CCH; c++) {
            float wv = wrow[c];
            ull wp; PACK2(wp, wv, wv);
            FMA2(accA, wp, *(const ull*)&hsA[c]);
            FMA2(accB, wp, *(const ull*)&hsB[c]);
        }
    }

    float fv[4];
    {
        float a0,a1,a2,a3;
        UNPACK2(a0,a1,accA); UNPACK2(a2,a3,accB);
        fv[0] = 1.0f/(1.0f + __expf(-a0));
        fv[1] = 1.0f/(1.0f + __expf(-a1));
        fv[2] = 1.0f/(1.0f + __expf(-a2));
        fv[3] = 1.0f/(1.0f + __expf(-a3));
    }
    #pragma unroll
    for (int px = 0; px < 4; px++) g_f[(pix0+px)*CCH + t] = fv[px];

    // ||f||^2 per pixel via warp shuffles
    float v0 = fv[0]*fv[0], v1 = fv[1]*fv[1], v2 = fv[2]*fv[2], v3 = fv[3]*fv[3];
    #pragma unroll
    for (int o = 16; o > 0; o >>= 1) {
        v0 += __shfl_xor_sync(0xFFFFFFFFu, v0, o);
        v1 += __shfl_xor_sync(0xFFFFFFFFu, v1, o);
        v2 += __shfl_xor_sync(0xFFFFFFFFu, v2, o);
        v3 += __shfl_xor_sync(0xFFFFFFFFu, v3, o);
    }
    if ((t & 31) == 0) {
        int w = t >> 5;
        part2[w][0] = v0; part2[w][1] = v1; part2[w][2] = v2; part2[w][3] = v3;
    }
    __syncthreads();
    if (t < 4)
        g_f2[pix0 + t] = part2[0][t] + part2[1][t] + part2[2][t] + part2[3][t];
}

// ---------------- kernel 2: distance GEMM (f32x2) + sqrt epilogue ----------------
#define BM 64
#define BN 64
#define BK 32
#define ASTR (2*BM + 4)
__global__ void dist_kernel(const float* __restrict__ protos) {
    __shared__ float As2[BK][ASTR];     // A duplicated: [a,a] pairs
    __shared__ float Bs[BK][BN + 4];
    const int tid = threadIdx.x;        // 256
    const int tx = tid & 15, ty = tid >> 4;
    const int m0 = blockIdx.y * BM;
    const int n0 = blockIdx.x * BN;

    ull acc[4][2];
    #pragma unroll
    for (int i = 0; i < 4; i++) { acc[i][0] = 0ull; acc[i][1] = 0ull; }

    for (int k0 = 0; k0 < CCH; k0 += BK) {
        #pragma unroll
        for (int l = 0; l < 2; l++) {
            int idx = tid + l*256;
            int row = idx >> 3;
            int kc4 = idx & 7;
            float4 v = make_float4(0,0,0,0);
            int m = m0 + row;
            if (m < NPIX) v = *(const float4*)&g_f[m*CCH + k0 + kc4*4];
            As2[kc4*4+0][2*row] = v.x; As2[kc4*4+0][2*row+1] = v.x;
            As2[kc4*4+1][2*row] = v.y; As2[kc4*4+1][2*row+1] = v.y;
            As2[kc4*4+2][2*row] = v.z; As2[kc4*4+2][2*row+1] = v.z;
            As2[kc4*4+3][2*row] = v.w; As2[kc4*4+3][2*row+1] = v.w;
            float4 u = make_float4(0,0,0,0);
            int n = n0 + row;
            if (n < NPROTO) u = *(const float4*)&protos[n*CCH + k0 + kc4*4];
            Bs[kc4*4+0][row] = u.x; Bs[kc4*4+1][row] = u.y;
            Bs[kc4*4+2][row] = u.z; Bs[kc4*4+3][row] = u.w;
        }
        __syncthreads();
        #pragma unroll
        for (int k = 0; k < BK; k++) {
            ulonglong2 a01 = *(const ulonglong2*)&As2[k][ty*8];
            ulonglong2 a23 = *(const ulonglong2*)&As2[k][ty*8+4];
            ulonglong2 bp  = *(const ulonglong2*)&Bs[k][tx*4];
            FMA2(acc[0][0], a01.x, bp.x); FMA2(acc[0][1], a01.x, bp.y);
            FMA2(acc[1][0], a01.y, bp.x); FMA2(acc[1][1], a01.y, bp.y);
            FMA2(acc[2][0], a23.x, bp.x); FMA2(acc[2][1], a23.x, bp.y);
            FMA2(acc[3][0], a23.y, bp.x); FMA2(acc[3][1], a23.y, bp.y);
        }
        __syncthreads();
    }

    #pragma unroll
    for (int i = 0; i < 4; i++) {
        int m = m0 + ty*4 + i;
        if (m >= NPIX) continue;
        int b = m / SP, s = m % SP;
        float f2 = g_f2[m];
        float c0,c1,c2,c3;
        UNPACK2(c0, c1, acc[i][0]);
        UNPACK2(c2, c3, acc[i][1]);
        float cr[4] = {c0, c1, c2, c3};
        #pragma unroll
        for (int j = 0; j < 4; j++) {
            int n = n0 + tx*4 + j;
            if (n >= NPROTO) continue;
            float d2 = f2 + g_p2[n] - 2.0f*cr[j];
            d2 = fmaxf(d2, 0.0f);
            g_dist[(b*NPROTO + n)*SP + s] = sqrtf(d2 + 1e-12f);
        }
    }
}

// ---------------- kernel 3: bilinear x16 upsample + min + act + logits atomics ----------------
__device__ __forceinline__ void bil_coef(int o, int lim, int& ia, int& ib, float& w) {
    int r = o & 15, q = o >> 4;
    int i0;
    if (r >= 8) { i0 = q;     w = (float)(r - 8) * 0.0625f + 0.03125f; }
    else        { i0 = q - 1; w = (float)(r + 8) * 0.0625f + 0.03125f; }
    ia = i0 < 0 ? 0 : i0;
    ib = (i0 + 1 > lim) ? lim : i0 + 1;
}

__global__ void upsample_kernel(float* __restrict__ up, float* __restrict__ out_min,
                                const float* __restrict__ last_w,
                                float* __restrict__ out_logits) {
    const int bp = blockIdx.x;                 // b*NPROTO + p
    const int t = threadIdx.x;                 // 256
    __shared__ float src[SP];
    __shared__ __align__(16) float hrow[HH][IMG];   // 12.25 KB
    __shared__ float red[256];
    __shared__ float s_act;

    if (t < SP) src[t] = g_dist[bp*SP + t];
    __syncthreads();

    // horizontal interpolation: 14 rows x 224
    for (int i = t; i < HH*IMG; i += 256) {
        int row = i / IMG, x = i - row*IMG;
        int xa, xb; float w;
        bil_coef(x, WW - 1, xa, xb, w);
        hrow[row][x] = (1.0f - w)*src[row*WW + xa] + w*src[row*WW + xb];
    }
    __syncthreads();

    float mn = INFINITY;
    float* dst = up + (size_t)bp * UPSZ;
    // 224 rows x 56 float4 = 12544 float4, contiguous in v
    for (int v = t; v < IMG*UPF4; v += 256) {
        int y = v / UPF4, xv = (v - y*UPF4) * 4;
        int ya, yb; float w;
        bil_coef(y, HH - 1, ya, yb, w);
        float4 A = *(const float4*)&hrow[ya][xv];
        float4 B = *(const float4*)&hrow[yb][xv];
        float4 o;
        float wi = 1.0f - w;
        o.x = wi*A.x + w*B.x;
        o.y = wi*A.y + w*B.y;
        o.z = wi*A.z + w*B.z;
        o.w = wi*A.w + w*B.w;
        mn = fminf(mn, fminf(fminf(o.x, o.y), fminf(o.z, o.w)));
        __stcs((float4*)&dst[(size_t)v*4], o);
    }

    red[t] = mn;
    __syncthreads();
    #pragma unroll
    for (int off = 128; off > 0; off >>= 1) {
        if (t < off) red[t] = fminf(red[t], red[t + off]);
        __syncthreads();
    }
    if (t == 0) {
        float m = red[0];
        out_min[bp] = m;
        s_act = logf((m + 1.0f) / (m + 1e-4f));
    }
    __syncthreads();

    // scatter logits contribution: logits[b][cls] += act * last_w[cls][p]
    if (t < NCLS) {
        int b = bp / NPROTO, p = bp - b*NPROTO;
        float contrib = s_act * __ldg(&last_w[t*NPROTO + p]);
        atomicAdd(&out_logits[b*NCLS + t], contrib);
    }
}

// ---------------- launch ----------------
extern "C" void kernel_launch(void* const* d_in, const int* in_sizes, int n_in,
                              void* d_out, int out_size) {
    const float* fmap   = (const float*)d_in[0];
    const float* w1     = (const float*)d_in[1];
    const float* b1     = (const float*)d_in[2];
    const float* w2     = (const float*)d_in[3];
    const float* b2     = (const float*)d_in[4];
    const float* protos = (const float*)d_in[5];
    const float* last_w = (const float*)d_in[6];

    float* out        = (float*)d_out;
    float* out_logits = out;                               // 4*200
    float* out_min    = out + BATCH*NCLS;                  // 4*2000
    float* out_up     = out + BATCH*NCLS + BATCH*NPROTO;   // 4*2000*224*224

    const int addon_blocks = NPIX/4;                       // 196
    const int p2_blocks = (NPROTO + 3)/4;                  // 500
    prep_kernel<<<addon_blocks + p2_blocks, CCH>>>(fmap, w1, b1, w2, b2, protos, out_logits);
    dist_kernel<<<dim3((NPROTO + BN - 1)/BN, (NPIX + BM - 1)/BM), 256>>>(protos);
    upsample_kernel<<<BATCH*NPROTO, 256>>>(out_up, out_min, last_w, out_logits);
}

// round 5
// speedup vs baseline: 1.5939x; 1.0636x over previous
#include <cuda_runtime.h>
#include <math.h>

#define BATCH   4
#define CCH     128
#define HH      14
#define WW      14
#define SP      (HH*WW)        // 196
#define NPIX    (BATCH*SP)     // 784
#define NPROTO  2000
#define NCLS    200
#define IMG     224
#define UPF4    (IMG/4)        // 56
#define UPSZ    (IMG*IMG)      // 50176

typedef unsigned long long ull;

// packed f32x2 helpers (sm_103a FFMA2 — only via PTX)
#define PACK2(d, lo, hi)  asm("mov.b64 %0, {%1, %2};" : "=l"(d) : "f"(lo), "f"(hi))
#define UNPACK2(lo, hi, s) asm("mov.b64 {%0, %1}, %2;" : "=f"(lo), "=f"(hi) : "l"(s))
#define FMA2(acc, a, b)   asm("fma.rn.f32x2 %0, %1, %2, %3;" : "=l"(acc) : "l"(a), "l"(b), "l"(acc))

// ---------------- scratch ----------------
__device__ __align__(16) float g_x[NPIX*CCH];       // transposed fmap, pixel-major
__device__ __align__(16) float g_h[NPIX*CCH];       // relu(layer1), pixel-major
__device__ __align__(16) float g_f[NPIX*CCH];       // sigmoid features, pixel-major
__device__ __align__(16) float g_f2[NPIX];
__device__ __align__(16) float g_p2[NPROTO];
__device__ __align__(16) float g_dist[BATCH*NPROTO*SP];

// ---------------- kernel 0: transpose fmap -> pixel-major, p2, zero accumulators ----
#define TR_BLOCKS (BATCH*4*7)   // 4 c-tiles x 7 s-tiles per batch = 112
__global__ void prep0_kernel(const float* __restrict__ fmap,
                             const float* __restrict__ protos,
                             float* __restrict__ out_logits) {
    const int t = threadIdx.x;   // 128
    if (blockIdx.x == 0) {
        for (int i = t; i < BATCH*NCLS; i += 128) out_logits[i] = 0.0f;
        for (int i = t; i < NPIX; i += 128) g_f2[i] = 0.0f;
    }
    if (blockIdx.x >= TR_BLOCKS) {
        // ---- ||p||^2: 4 protos per block, 32 lanes each ----
        int p = (blockIdx.x - TR_BLOCKS) * 4 + (t >> 5);
        int lane = t & 31;
        if (p >= NPROTO) return;
        float s = 0.0f;
        #pragma unroll
        for (int c = lane; c < CCH; c += 32) {
            float v = protos[p*CCH + c];
            s = fmaf(v, v, s);
        }
        #pragma unroll
        for (int o = 16; o > 0; o >>= 1) s += __shfl_xor_sync(0xFFFFFFFFu, s, o);
        if (lane == 0) g_p2[p] = s;
        return;
    }

    // ---- 32x32 tile transpose: fmap[b][c][s] -> g_x[b*SP+s][c] ----
    const int tb = blockIdx.x;
    const int b  = tb / 28;
    const int rem = tb - b*28;
    const int tc = rem / 7;           // c-tile 0..3
    const int ts = rem - tc*7;        // s-tile 0..6
    const int tx = t & 31;            // s within tile (load) / c within tile (store)
    const int ty = t >> 5;            // 0..3

    __shared__ float sm[32][33];

    #pragma unroll
    for (int r = 0; r < 8; r++) {
        int c_local = ty*8 + r;
        int s = ts*32 + tx;
        if (s < SP)
            sm[c_local][tx] = fmap[(b*CCH + tc*32 + c_local)*SP + s];
    }
    __syncthreads();
    #pragma unroll
    for (int r = 0; r < 8; r++) {
        int s_local = ty*8 + r;
        int s = ts*32 + s_local;
        if (s < SP)
            g_x[(b*SP + s)*CCH + tc*32 + tx] = sm[tx][s_local];
    }
}

// ---------------- GEMM tiling shared by addon gemms and dist ----------------
#define BM 64
#define BN 64
#define BK 32

// addon gemm: out[m][n] = act( sum_k A[m][k]*W[n][k] + bias[n] )
// LAYER = 1: relu -> g_h ; LAYER = 2: sigmoid -> g_f + f2 atomics
template<int LAYER>
__global__ void addon_gemm_kernel(const float* __restrict__ A,
                                  const float* __restrict__ W,
                                  const float* __restrict__ bias,
                                  float* __restrict__ out) {
    __shared__ float As[BK][BM + 4];
    __shared__ float Bs[BK][BN + 4];
    const int tid = threadIdx.x;        // 256
    const int tx = tid & 15, ty = tid >> 4;
    const int m0 = blockIdx.y * BM;
    const int n0 = blockIdx.x * BN;

    float acc[4][4] = {};

    for (int k0 = 0; k0 < CCH; k0 += BK) {
        #pragma unroll
        for (int l = 0; l < 2; l++) {
            int idx = tid + l*256;
            int row = idx >> 3;
            int kc4 = idx & 7;
            float4 v = make_float4(0,0,0,0);
            int m = m0 + row;
            if (m < NPIX) v = *(const float4*)&A[m*CCH + k0 + kc4*4];
            As[kc4*4+0][row] = v.x; As[kc4*4+1][row] = v.y;
            As[kc4*4+2][row] = v.z; As[kc4*4+3][row] = v.w;
            int n = n0 + row;
            float4 u = *(const float4*)&W[n*CCH + k0 + kc4*4];
            Bs[kc4*4+0][row] = u.x; Bs[kc4*4+1][row] = u.y;
            Bs[kc4*4+2][row] = u.z; Bs[kc4*4+3][row] = u.w;
        }
        __syncthreads();
        #pragma unroll
        for (int k = 0; k < BK; k++) {
            float4 a4 = *(const float4*)&As[k][ty*4];
            float4 b4 = *(const float4*)&Bs[k][tx*4];
            float a[4] = {a4.x, a4.y, a4.z, a4.w};
            float bb[4] = {b4.x, b4.y, b4.z, b4.w};
            #pragma unroll
            for (int i = 0; i < 4; i++)
                #pragma unroll
                for (int j = 0; j < 4; j++)
                    acc[i][j] = fmaf(a[i], bb[j], acc[i][j]);
        }
        __syncthreads();
    }

    float bs[4];
    #pragma unroll
    for (int j = 0; j < 4; j++) bs[j] = bias[n0 + tx*4 + j];

    #pragma unroll
    for (int i = 0; i < 4; i++) {
        int m = m0 + ty*4 + i;
        bool valid = (m < NPIX);
        float f2p = 0.0f;
        #pragma unroll
        for (int j = 0; j < 4; j++) {
            float v = acc[i][j] + bs[j];
            if (LAYER == 1) {
                v = fmaxf(v, 0.0f);
            } else {
                v = 1.0f / (1.0f + __expf(-v));
                f2p = fmaf(v, v, f2p);
            }
            if (valid) out[m*CCH + n0 + tx*4 + j] = v;
        }
        if (LAYER == 2) {
            // sum f2p across the 16 tx lanes (lanes differing in bits 0..3)
            #pragma unroll
            for (int o = 8; o > 0; o >>= 1)
                f2p += __shfl_xor_sync(0xFFFFFFFFu, f2p, o);
            if (tx == 0 && valid) atomicAdd(&g_f2[m], f2p);
        }
    }
}

// ---------------- distance GEMM (f32x2) + sqrt epilogue ----------------
#define ASTR (2*BM + 4)
__global__ void dist_kernel(const float* __restrict__ protos) {
    __shared__ float As2[BK][ASTR];     // A duplicated: [a,a] pairs
    __shared__ float Bs[BK][BN + 4];
    const int tid = threadIdx.x;        // 256
    const int tx = tid & 15, ty = tid >> 4;
    const int m0 = blockIdx.y * BM;
    const int n0 = blockIdx.x * BN;

    ull acc[4][2];
    #pragma unroll
    for (int i = 0; i < 4; i++) { acc[i][0] = 0ull; acc[i][1] = 0ull; }

    for (int k0 = 0; k0 < CCH; k0 += BK) {
        #pragma unroll
        for (int l = 0; l < 2; l++) {
            int idx = tid + l*256;
            int row = idx >> 3;
            int kc4 = idx & 7;
            float4 v = make_float4(0,0,0,0);
            int m = m0 + row;
            if (m < NPIX) v = *(const float4*)&g_f[m*CCH + k0 + kc4*4];
            As2[kc4*4+0][2*row] = v.x; As2[kc4*4+0][2*row+1] = v.x;
            As2[kc4*4+1][2*row] = v.y; As2[kc4*4+1][2*row+1] = v.y;
            As2[kc4*4+2][2*row] = v.z; As2[kc4*4+2][2*row+1] = v.z;
            As2[kc4*4+3][2*row] = v.w; As2[kc4*4+3][2*row+1] = v.w;
            float4 u = make_float4(0,0,0,0);
            int n = n0 + row;
            if (n < NPROTO) u = *(const float4*)&protos[n*CCH + k0 + kc4*4];
            Bs[kc4*4+0][row] = u.x; Bs[kc4*4+1][row] = u.y;
            Bs[kc4*4+2][row] = u.z; Bs[kc4*4+3][row] = u.w;
        }
        __syncthreads();
        #pragma unroll
        for (int k = 0; k < BK; k++) {
            ulonglong2 a01 = *(const ulonglong2*)&As2[k][ty*8];
            ulonglong2 a23 = *(const ulonglong2*)&As2[k][ty*8+4];
            ulonglong2 bp  = *(const ulonglong2*)&Bs[k][tx*4];
            FMA2(acc[0][0], a01.x, bp.x); FMA2(acc[0][1], a01.x, bp.y);
            FMA2(acc[1][0], a01.y, bp.x); FMA2(acc[1][1], a01.y, bp.y);
            FMA2(acc[2][0], a23.x, bp.x); FMA2(acc[2][1], a23.x, bp.y);
            FMA2(acc[3][0], a23.y, bp.x); FMA2(acc[3][1], a23.y, bp.y);
        }
        __syncthreads();
    }

    #pragma unroll
    for (int i = 0; i < 4; i++) {
        int m = m0 + ty*4 + i;
        if (m >= NPIX) continue;
        int b = m / SP, s = m % SP;
        float f2 = g_f2[m];
        float c0,c1,c2,c3;
        UNPACK2(c0, c1, acc[i][0]);
        UNPACK2(c2, c3, acc[i][1]);
        float cr[4] = {c0, c1, c2, c3};
        #pragma unroll
        for (int j = 0; j < 4; j++) {
            int n = n0 + tx*4 + j;
            if (n >= NPROTO) continue;
            float d2 = f2 + g_p2[n] - 2.0f*cr[j];
            d2 = fmaxf(d2, 0.0f);
            g_dist[(b*NPROTO + n)*SP + s] = sqrtf(d2 + 1e-12f);
        }
    }
}

// ---------------- bilinear x16 upsample + min + act + logits atomics ----------------
__device__ __forceinline__ void bil_coef(int o, int lim, int& ia, int& ib, float& w) {
    int r = o & 15, q = o >> 4;
    int i0;
    if (r >= 8) { i0 = q;     w = (float)(r - 8) * 0.0625f + 0.03125f; }
    else        { i0 = q - 1; w = (float)(r + 8) * 0.0625f + 0.03125f; }
    ia = i0 < 0 ? 0 : i0;
    ib = (i0 + 1 > lim) ? lim : i0 + 1;
}

__global__ void upsample_kernel(float* __restrict__ up, float* __restrict__ out_min,
                                const float* __restrict__ last_w,
                                float* __restrict__ out_logits) {
    const int bp = blockIdx.x;                 // b*NPROTO + p
    const int t = threadIdx.x;                 // 256
    __shared__ float src[SP];
    __shared__ __align__(16) float hrow[HH][IMG];   // 12.25 KB
    __shared__ float red[256];
    __shared__ float s_act;

    if (t < SP) src[t] = g_dist[bp*SP + t];
    __syncthreads();

    // horizontal interpolation: 14 rows x 224
    for (int i = t; i < HH*IMG; i += 256) {
        int row = i / IMG, x = i - row*IMG;
        int xa, xb; float w;
        bil_coef(x, WW - 1, xa, xb, w);
        hrow[row][x] = (1.0f - w)*src[row*WW + xa] + w*src[row*WW + xb];
    }
    __syncthreads();

    float mn = INFINITY;
    float* dst = up + (size_t)bp * UPSZ;
    for (int v = t; v < IMG*UPF4; v += 256) {
        int y = v / UPF4, xv = (v - y*UPF4) * 4;
        int ya, yb; float w;
        bil_coef(y, HH - 1, ya, yb, w);
        float4 A = *(const float4*)&hrow[ya][xv];
        float4 B = *(const float4*)&hrow[yb][xv];
        float4 o;
        float wi = 1.0f - w;
        o.x = wi*A.x + w*B.x;
        o.y = wi*A.y + w*B.y;
        o.z = wi*A.z + w*B.z;
        o.w = wi*A.w + w*B.w;
        mn = fminf(mn, fminf(fminf(o.x, o.y), fminf(o.z, o.w)));
        __stcs((float4*)&dst[(size_t)v*4], o);
    }

    red[t] = mn;
    __syncthreads();
    #pragma unroll
    for (int off = 128; off > 0; off >>= 1) {
        if (t < off) red[t] = fminf(red[t], red[t + off]);
        __syncthreads();
    }
    if (t == 0) {
        float m = red[0];
        out_min[bp] = m;
        s_act = logf((m + 1.0f) / (m + 1e-4f));
    }
    __syncthreads();

    // scatter logits contribution: logits[b][cls] += act * last_w[cls][p]
    if (t < NCLS) {
        int b = bp / NPROTO, p = bp - b*NPROTO;
        float contrib = s_act * __ldg(&last_w[t*NPROTO + p]);
        atomicAdd(&out_logits[b*NCLS + t], contrib);
    }
}

// ---------------- launch ----------------
extern "C" void kernel_launch(void* const* d_in, const int* in_sizes, int n_in,
                              void* d_out, int out_size) {
    const float* fmap   = (const float*)d_in[0];
    const float* w1     = (const float*)d_in[1];
    const float* b1     = (const float*)d_in[2];
    const float* w2     = (const float*)d_in[3];
    const float* b2     = (const float*)d_in[4];
    const float* protos = (const float*)d_in[5];
    const float* last_w = (const float*)d_in[6];

    float* out        = (float*)d_out;
    float* out_logits = out;                               // 4*200
    float* out_min    = out + BATCH*NCLS;                  // 4*2000
    float* out_up     = out + BATCH*NCLS + BATCH*NPROTO;   // 4*2000*224*224

    float* gx; cudaGetSymbolAddress((void**)&gx, g_x);
    float* gh; cudaGetSymbolAddress((void**)&gh, g_h);
    float* gf; cudaGetSymbolAddress((void**)&gf, g_f);

    const int p2_blocks = (NPROTO + 3)/4;                  // 500
    prep0_kernel<<<TR_BLOCKS + p2_blocks, 128>>>(fmap, protos, out_logits);
    dim3 ggrid(CCH/BN, (NPIX + BM - 1)/BM);                // (2, 13)
    addon_gemm_kernel<1><<<ggrid, 256>>>(gx, w1, b1, gh);
    addon_gemm_kernel<2><<<ggrid, 256>>>(gh, w2, b2, gf);
    dist_kernel<<<dim3((NPROTO + BN - 1)/BN, (NPIX + BM - 1)/BM), 256>>>(protos);
    upsample_kernel<<<BATCH*NPROTO, 256>>>(out_up, out_min, last_w, out_logits);
}

// round 6
// speedup vs baseline: 1.5970x; 1.0019x over previous
#include <cuda_runtime.h>
#include <math.h>

#define BATCH   4
#define CCH     128
#define HH      14
#define WW      14
#define SP      (HH*WW)        // 196
#define NPIX    (BATCH*SP)     // 784
#define NPROTO  2000
#define NCLS    200
#define IMG     224
#define UPF4    (IMG/4)        // 56
#define UPSZ    (IMG*IMG)      // 50176

// ---------------- scratch ----------------
__device__ __align__(16) float g_x[NPIX*CCH];       // transposed fmap, pixel-major
__device__ __align__(16) float g_h[NPIX*CCH];       // relu(layer1), pixel-major
__device__ __align__(16) float g_f[NPIX*CCH];       // sigmoid features, pixel-major
__device__ __align__(16) float g_f2[NPIX];
__device__ __align__(16) float g_p2[NPROTO];
__device__ __align__(16) float g_dist[BATCH*NPROTO*SP];

// ---------------- kernel 0: transpose fmap -> pixel-major, p2, zero accumulators ----
#define TR_BLOCKS (BATCH*4*7)   // 4 c-tiles x 7 s-tiles per batch = 112
__global__ void prep0_kernel(const float* __restrict__ fmap,
                             const float* __restrict__ protos,
                             float* __restrict__ out_logits) {
    const int t = threadIdx.x;   // 128
    if (blockIdx.x == 0) {
        for (int i = t; i < BATCH*NCLS; i += 128) out_logits[i] = 0.0f;
        for (int i = t; i < NPIX; i += 128) g_f2[i] = 0.0f;
    }
    if (blockIdx.x >= TR_BLOCKS) {
        // ---- ||p||^2: 4 protos per block, 32 lanes each ----
        int p = (blockIdx.x - TR_BLOCKS) * 4 + (t >> 5);
        int lane = t & 31;
        if (p >= NPROTO) return;
        float s = 0.0f;
        #pragma unroll
        for (int c = lane; c < CCH; c += 32) {
            float v = protos[p*CCH + c];
            s = fmaf(v, v, s);
        }
        #pragma unroll
        for (int o = 16; o > 0; o >>= 1) s += __shfl_xor_sync(0xFFFFFFFFu, s, o);
        if (lane == 0) g_p2[p] = s;
        return;
    }

    // ---- 32x32 tile transpose: fmap[b][c][s] -> g_x[b*SP+s][c] ----
    const int tb = blockIdx.x;
    const int b  = tb / 28;
    const int rem = tb - b*28;
    const int tc = rem / 7;           // c-tile 0..3
    const int ts = rem - tc*7;        // s-tile 0..6
    const int tx = t & 31;
    const int ty = t >> 5;            // 0..3

    __shared__ float sm[32][33];

    #pragma unroll
    for (int r = 0; r < 8; r++) {
        int c_local = ty*8 + r;
        int s = ts*32 + tx;
        if (s < SP)
            sm[c_local][tx] = fmap[(b*CCH + tc*32 + c_local)*SP + s];
    }
    __syncthreads();
    #pragma unroll
    for (int r = 0; r < 8; r++) {
        int s_local = ty*8 + r;
        int s = ts*32 + s_local;
        if (s < SP)
            g_x[(b*SP + s)*CCH + tc*32 + tx] = sm[tx][s_local];
    }
}

// ---------------- addon gemms: 64x64 tile, 4x4 micro ----------------
#define BM 64
#define BN 64
#define BK 32

// addon gemm: out[m][n] = act( sum_k A[m][k]*W[n][k] + bias[n] )
// LAYER = 1: relu -> g_h ; LAYER = 2: sigmoid -> g_f + f2 atomics
template<int LAYER>
__global__ void addon_gemm_kernel(const float* __restrict__ A,
                                  const float* __restrict__ W,
                                  const float* __restrict__ bias,
                                  float* __restrict__ out) {
    __shared__ float As[BK][BM + 4];
    __shared__ float Bs[BK][BN + 4];
    const int tid = threadIdx.x;        // 256
    const int tx = tid & 15, ty = tid >> 4;
    const int m0 = blockIdx.y * BM;
    const int n0 = blockIdx.x * BN;

    float acc[4][4] = {};

    for (int k0 = 0; k0 < CCH; k0 += BK) {
        #pragma unroll
        for (int l = 0; l < 2; l++) {
            int idx = tid + l*256;
            int row = idx >> 3;
            int kc4 = idx & 7;
            float4 v = make_float4(0,0,0,0);
            int m = m0 + row;
            if (m < NPIX) v = *(const float4*)&A[m*CCH + k0 + kc4*4];
            As[kc4*4+0][row] = v.x; As[kc4*4+1][row] = v.y;
            As[kc4*4+2][row] = v.z; As[kc4*4+3][row] = v.w;
            int n = n0 + row;
            float4 u = *(const float4*)&W[n*CCH + k0 + kc4*4];
            Bs[kc4*4+0][row] = u.x; Bs[kc4*4+1][row] = u.y;
            Bs[kc4*4+2][row] = u.z; Bs[kc4*4+3][row] = u.w;
        }
        __syncthreads();
        #pragma unroll
        for (int k = 0; k < BK; k++) {
            float4 a4 = *(const float4*)&As[k][ty*4];
            float4 b4 = *(const float4*)&Bs[k][tx*4];
            float a[4] = {a4.x, a4.y, a4.z, a4.w};
            float bb[4] = {b4.x, b4.y, b4.z, b4.w};
            #pragma unroll
            for (int i = 0; i < 4; i++)
                #pragma unroll
                for (int j = 0; j < 4; j++)
                    acc[i][j] = fmaf(a[i], bb[j], acc[i][j]);
        }
        __syncthreads();
    }

    float bs[4];
    #pragma unroll
    for (int j = 0; j < 4; j++) bs[j] = bias[n0 + tx*4 + j];

    #pragma unroll
    for (int i = 0; i < 4; i++) {
        int m = m0 + ty*4 + i;
        bool valid = (m < NPIX);
        float f2p = 0.0f;
        #pragma unroll
        for (int j = 0; j < 4; j++) {
            float v = acc[i][j] + bs[j];
            if (LAYER == 1) {
                v = fmaxf(v, 0.0f);
            } else {
                v = 1.0f / (1.0f + __expf(-v));
                f2p = fmaf(v, v, f2p);
            }
            if (valid) out[m*CCH + n0 + tx*4 + j] = v;
        }
        if (LAYER == 2) {
            #pragma unroll
            for (int o = 8; o > 0; o >>= 1)
                f2p += __shfl_xor_sync(0xFFFFFFFFu, f2p, o);
            if (tx == 0 && valid) atomicAdd(&g_f2[m], f2p);
        }
    }
}

// ---------------- distance GEMM: 128x64 tile, 8x4 micro (1.5 B LDS / FMA) ----------------
#define DBM 128
#define DBN 64
#define DBK 32
__global__ void dist_kernel(const float* __restrict__ protos) {
    __shared__ float As[DBK][DBM + 4];
    __shared__ float Bs[DBK][DBN + 4];
    const int tid = threadIdx.x;        // 256
    const int tx = tid & 15, ty = tid >> 4;
    const int m0 = blockIdx.y * DBM;
    const int n0 = blockIdx.x * DBN;

    float acc[8][4] = {};

    for (int k0 = 0; k0 < CCH; k0 += DBK) {
        // A: 128 rows x 8 float4 = 1024 float4 -> 4 per thread
        #pragma unroll
        for (int l = 0; l < 4; l++) {
            int idx = tid + l*256;
            int row = idx >> 3;
            int kc4 = idx & 7;
            float4 v = make_float4(0,0,0,0);
            int m = m0 + row;
            if (m < NPIX) v = *(const float4*)&g_f[m*CCH + k0 + kc4*4];
            As[kc4*4+0][row] = v.x; As[kc4*4+1][row] = v.y;
            As[kc4*4+2][row] = v.z; As[kc4*4+3][row] = v.w;
        }
        // B: 64 rows x 8 float4 = 512 float4 -> 2 per thread
        #pragma unroll
        for (int l = 0; l < 2; l++) {
            int idx = tid + l*256;
            int row = idx >> 3;
            int kc4 = idx & 7;
            float4 u = make_float4(0,0,0,0);
            int n = n0 + row;
            if (n < NPROTO) u = *(const float4*)&protos[n*CCH + k0 + kc4*4];
            Bs[kc4*4+0][row] = u.x; Bs[kc4*4+1][row] = u.y;
            Bs[kc4*4+2][row] = u.z; Bs[kc4*4+3][row] = u.w;
        }
        __syncthreads();
        #pragma unroll
        for (int k = 0; k < DBK; k++) {
            float4 a0 = *(const float4*)&As[k][ty*8];
            float4 a1 = *(const float4*)&As[k][ty*8 + 4];
            float4 b4 = *(const float4*)&Bs[k][tx*4];
            float a[8] = {a0.x, a0.y, a0.z, a0.w, a1.x, a1.y, a1.z, a1.w};
            float bb[4] = {b4.x, b4.y, b4.z, b4.w};
            #pragma unroll
            for (int i = 0; i < 8; i++)
                #pragma unroll
                for (int j = 0; j < 4; j++)
                    acc[i][j] = fmaf(a[i], bb[j], acc[i][j]);
        }
        __syncthreads();
    }

    #pragma unroll
    for (int i = 0; i < 8; i++) {
        int m = m0 + ty*8 + i;
        if (m >= NPIX) continue;
        int b = m / SP, s = m % SP;
        float f2 = g_f2[m];
        #pragma unroll
        for (int j = 0; j < 4; j++) {
            int n = n0 + tx*4 + j;
            if (n >= NPROTO) continue;
            float d2 = f2 + g_p2[n] - 2.0f*acc[i][j];
            d2 = fmaxf(d2, 0.0f);
            g_dist[(b*NPROTO + n)*SP + s] = sqrtf(d2 + 1e-12f);
        }
    }
}

// ---------------- bilinear x16 upsample + min + act + logits atomics ----------------
__device__ __forceinline__ void bil_coef(int o, int lim, int& ia, int& ib, float& w) {
    int r = o & 15, q = o >> 4;
    int i0;
    if (r >= 8) { i0 = q;     w = (float)(r - 8) * 0.0625f + 0.03125f; }
    else        { i0 = q - 1; w = (float)(r + 8) * 0.0625f + 0.03125f; }
    ia = i0 < 0 ? 0 : i0;
    ib = (i0 + 1 > lim) ? lim : i0 + 1;
}

__global__ void upsample_kernel(float* __restrict__ up, float* __restrict__ out_min,
                                const float* __restrict__ last_w,
                                float* __restrict__ out_logits) {
    const int bp = blockIdx.x;                 // b*NPROTO + p
    const int t = threadIdx.x;                 // 256
    __shared__ float src[SP];
    __shared__ __align__(16) float hrow[HH][IMG];   // 12.25 KB
    __shared__ float red[256];
    __shared__ float s_act;

    if (t < SP) src[t] = g_dist[bp*SP + t];
    __syncthreads();

    // horizontal interpolation: 14 rows x 224
    for (int i = t; i < HH*IMG; i += 256) {
        int row = i / IMG, x = i - row*IMG;
        int xa, xb; float w;
        bil_coef(x, WW - 1, xa, xb, w);
        hrow[row][x] = (1.0f - w)*src[row*WW + xa] + w*src[row*WW + xb];
    }
    __syncthreads();

    float mn = INFINITY;
    float* dst = up + (size_t)bp * UPSZ;
    for (int v = t; v < IMG*UPF4; v += 256) {
        int y = v / UPF4, xv = (v - y*UPF4) * 4;
        int ya, yb; float w;
        bil_coef(y, HH - 1, ya, yb, w);
        float4 A = *(const float4*)&hrow[ya][xv];
        float4 B = *(const float4*)&hrow[yb][xv];
        float4 o;
        float wi = 1.0f - w;
        o.x = wi*A.x + w*B.x;
        o.y = wi*A.y + w*B.y;
        o.z = wi*A.z + w*B.z;
        o.w = wi*A.w + w*B.w;
        mn = fminf(mn, fminf(fminf(o.x, o.y), fminf(o.z, o.w)));
        __stcs((float4*)&dst[(size_t)v*4], o);
    }

    red[t] = mn;
    __syncthreads();
    #pragma unroll
    for (int off = 128; off > 0; off >>= 1) {
        if (t < off) red[t] = fminf(red[t], red[t + off]);
        __syncthreads();
    }
    if (t == 0) {
        float m = red[0];
        out_min[bp] = m;
        s_act = logf((m + 1.0f) / (m + 1e-4f));
    }
    __syncthreads();

    // scatter logits contribution: logits[b][cls] += act * last_w[cls][p]
    if (t < NCLS) {
        int b = bp / NPROTO, p = bp - b*NPROTO;
        float contrib = s_act * __ldg(&last_w[t*NPROTO + p]);
        atomicAdd(&out_logits[b*NCLS + t], contrib);
    }
}

// ---------------- launch ----------------
extern "C" void kernel_launch(void* const* d_in, const int* in_sizes, int n_in,
                              void* d_out, int out_size) {
    const float* fmap   = (const float*)d_in[0];
    const float* w1     = (const float*)d_in[1];
    const float* b1     = (const float*)d_in[2];
    const float* w2     = (const float*)d_in[3];
    const float* b2     = (const float*)d_in[4];
    const float* protos = (const float*)d_in[5];
    const float* last_w = (const float*)d_in[6];

    float* out        = (float*)d_out;
    float* out_logits = out;                               // 4*200
    float* out_min    = out + BATCH*NCLS;                  // 4*2000
    float* out_up     = out + BATCH*NCLS + BATCH*NPROTO;   // 4*2000*224*224

    float* gx; cudaGetSymbolAddress((void**)&gx, g_x);
    float* gh; cudaGetSymbolAddress((void**)&gh, g_h);
    float* gf; cudaGetSymbolAddress((void**)&gf, g_f);

    const int p2_blocks = (NPROTO + 3)/4;                  // 500
    prep0_kernel<<<TR_BLOCKS + p2_blocks, 128>>>(fmap, protos, out_logits);
    dim3 ggrid(CCH/BN, (NPIX + BM - 1)/BM);                // (2, 13)
    addon_gemm_kernel<1><<<ggrid, 256>>>(gx, w1, b1, gh);
    addon_gemm_kernel<2><<<ggrid, 256>>>(gh, w2, b2, gf);
    dist_kernel<<<dim3((NPROTO + DBN - 1)/DBN, (NPIX + DBM - 1)/DBM), 256>>>(protos);
    upsample_kernel<<<BATCH*NPROTO, 256>>>(out_up, out_min, last_w, out_logits);
}

// round 7
// speedup vs baseline: 1.6167x; 1.0123x over previous
#include <cuda_runtime.h>
#include <math.h>

#define BATCH   4
#define CCH     128
#define HH      14
#define WW      14
#define SP      (HH*WW)        // 196
#define NPIX    (BATCH*SP)     // 784
#define NPROTO  2000
#define NCLS    200
#define IMG     224
#define UPF4    (IMG/4)        // 56
#define UPSZ    (IMG*IMG)      // 50176

// ---------------- scratch ----------------
__device__ __align__(16) float g_x[NPIX*CCH];       // transposed fmap, pixel-major
__device__ __align__(16) float g_h[NPIX*CCH];       // relu(layer1), pixel-major
__device__ __align__(16) float g_f[NPIX*CCH];       // sigmoid features, pixel-major
__device__ __align__(16) float g_f2[NPIX];
__device__ __align__(16) float g_p2[NPROTO];
// dist layout: [s][b][n]  ->  index (s*BATCH + b)*NPROTO + n   (coalesced dist stores)
__device__ __align__(16) float g_dist[SP*BATCH*NPROTO];

// ---------------- kernel 0: transpose fmap -> pixel-major, p2, zero accumulators ----
#define TR_BLOCKS (BATCH*4*7)   // 4 c-tiles x 7 s-tiles per batch = 112
__global__ void prep0_kernel(const float* __restrict__ fmap,
                             const float* __restrict__ protos,
                             float* __restrict__ out_logits) {
    const int t = threadIdx.x;   // 128
    if (blockIdx.x == 0) {
        for (int i = t; i < BATCH*NCLS; i += 128) out_logits[i] = 0.0f;
        for (int i = t; i < NPIX; i += 128) g_f2[i] = 0.0f;
    }
    if (blockIdx.x >= TR_BLOCKS) {
        // ---- ||p||^2: 4 protos per block, 32 lanes each ----
        int p = (blockIdx.x - TR_BLOCKS) * 4 + (t >> 5);
        int lane = t & 31;
        if (p >= NPROTO) return;
        float s = 0.0f;
        #pragma unroll
        for (int c = lane; c < CCH; c += 32) {
            float v = protos[p*CCH + c];
            s = fmaf(v, v, s);
        }
        #pragma unroll
        for (int o = 16; o > 0; o >>= 1) s += __shfl_xor_sync(0xFFFFFFFFu, s, o);
        if (lane == 0) g_p2[p] = s;
        return;
    }

    // ---- 32x32 tile transpose: fmap[b][c][s] -> g_x[b*SP+s][c] ----
    const int tb = blockIdx.x;
    const int b  = tb / 28;
    const int rem = tb - b*28;
    const int tc = rem / 7;           // c-tile 0..3
    const int ts = rem - tc*7;        // s-tile 0..6
    const int tx = t & 31;
    const int ty = t >> 5;            // 0..3

    __shared__ float sm[32][33];

    #pragma unroll
    for (int r = 0; r < 8; r++) {
        int c_local = ty*8 + r;
        int s = ts*32 + tx;
        if (s < SP)
            sm[c_local][tx] = fmap[(b*CCH + tc*32 + c_local)*SP + s];
    }
    __syncthreads();
    #pragma unroll
    for (int r = 0; r < 8; r++) {
        int s_local = ty*8 + r;
        int s = ts*32 + s_local;
        if (s < SP)
            g_x[(b*SP + s)*CCH + tc*32 + tx] = sm[tx][s_local];
    }
}

// ---------------- addon gemms: 64x64 tile, 4x4 micro ----------------
#define BM 64
#define BN 64
#define BK 32

// addon gemm: out[m][n] = act( sum_k A[m][k]*W[n][k] + bias[n] )
// LAYER = 1: relu -> g_h ; LAYER = 2: sigmoid -> g_f + f2 atomics
template<int LAYER>
__global__ void addon_gemm_kernel(const float* __restrict__ A,
                                  const float* __restrict__ W,
                                  const float* __restrict__ bias,
                                  float* __restrict__ out) {
    __shared__ float As[BK][BM + 4];
    __shared__ float Bs[BK][BN + 4];
    const int tid = threadIdx.x;        // 256
    const int tx = tid & 15, ty = tid >> 4;
    const int m0 = blockIdx.y * BM;
    const int n0 = blockIdx.x * BN;

    float acc[4][4] = {};

    for (int k0 = 0; k0 < CCH; k0 += BK) {
        #pragma unroll
        for (int l = 0; l < 2; l++) {
            int idx = tid + l*256;
            int row = idx >> 3;
            int kc4 = idx & 7;
            float4 v = make_float4(0,0,0,0);
            int m = m0 + row;
            if (m < NPIX) v = *(const float4*)&A[m*CCH + k0 + kc4*4];
            As[kc4*4+0][row] = v.x; As[kc4*4+1][row] = v.y;
            As[kc4*4+2][row] = v.z; As[kc4*4+3][row] = v.w;
            int n = n0 + row;
            float4 u = *(const float4*)&W[n*CCH + k0 + kc4*4];
            Bs[kc4*4+0][row] = u.x; Bs[kc4*4+1][row] = u.y;
            Bs[kc4*4+2][row] = u.z; Bs[kc4*4+3][row] = u.w;
        }
        __syncthreads();
        #pragma unroll
        for (int k = 0; k < BK; k++) {
            float4 a4 = *(const float4*)&As[k][ty*4];
            float4 b4 = *(const float4*)&Bs[k][tx*4];
            float a[4] = {a4.x, a4.y, a4.z, a4.w};
            float bb[4] = {b4.x, b4.y, b4.z, b4.w};
            #pragma unroll
            for (int i = 0; i < 4; i++)
                #pragma unroll
                for (int j = 0; j < 4; j++)
                    acc[i][j] = fmaf(a[i], bb[j], acc[i][j]);
        }
        __syncthreads();
    }

    float bs[4];
    #pragma unroll
    for (int j = 0; j < 4; j++) bs[j] = bias[n0 + tx*4 + j];

    #pragma unroll
    for (int i = 0; i < 4; i++) {
        int m = m0 + ty*4 + i;
        bool valid = (m < NPIX);
        float f2p = 0.0f;
        #pragma unroll
        for (int j = 0; j < 4; j++) {
            float v = acc[i][j] + bs[j];
            if (LAYER == 1) {
                v = fmaxf(v, 0.0f);
            } else {
                v = 1.0f / (1.0f + __expf(-v));
                f2p = fmaf(v, v, f2p);
            }
            if (valid) out[m*CCH + n0 + tx*4 + j] = v;
        }
        if (LAYER == 2) {
            #pragma unroll
            for (int o = 8; o > 0; o >>= 1)
                f2p += __shfl_xor_sync(0xFFFFFFFFu, f2p, o);
            if (tx == 0 && valid) atomicAdd(&g_f2[m], f2p);
        }
    }
}

// ---------------- distance GEMM: 128x64 tile, 8x4 micro, coalesced stores ----------------
#define DBM 128
#define DBN 64
#define DBK 32
__global__ void dist_kernel(const float* __restrict__ protos) {
    __shared__ float As[DBK][DBM + 4];
    __shared__ float Bs[DBK][DBN + 4];
    const int tid = threadIdx.x;        // 256
    const int tx = tid & 15, ty = tid >> 4;
    const int m0 = blockIdx.y * DBM;
    const int n0 = blockIdx.x * DBN;

    float acc[8][4] = {};

    for (int k0 = 0; k0 < CCH; k0 += DBK) {
        #pragma unroll
        for (int l = 0; l < 4; l++) {
            int idx = tid + l*256;
            int row = idx >> 3;
            int kc4 = idx & 7;
            float4 v = make_float4(0,0,0,0);
            int m = m0 + row;
            if (m < NPIX) v = *(const float4*)&g_f[m*CCH + k0 + kc4*4];
            As[kc4*4+0][row] = v.x; As[kc4*4+1][row] = v.y;
            As[kc4*4+2][row] = v.z; As[kc4*4+3][row] = v.w;
        }
        #pragma unroll
        for (int l = 0; l < 2; l++) {
            int idx = tid + l*256;
            int row = idx >> 3;
            int kc4 = idx & 7;
            float4 u = make_float4(0,0,0,0);
            int n = n0 + row;
            if (n < NPROTO) u = *(const float4*)&protos[n*CCH + k0 + kc4*4];
            Bs[kc4*4+0][row] = u.x; Bs[kc4*4+1][row] = u.y;
            Bs[kc4*4+2][row] = u.z; Bs[kc4*4+3][row] = u.w;
        }
        __syncthreads();
        #pragma unroll
        for (int k = 0; k < DBK; k++) {
            float4 a0 = *(const float4*)&As[k][ty*8];
            float4 a1 = *(const float4*)&As[k][ty*8 + 4];
            float4 b4 = *(const float4*)&Bs[k][tx*4];
            float a[8] = {a0.x, a0.y, a0.z, a0.w, a1.x, a1.y, a1.z, a1.w};
            float bb[4] = {b4.x, b4.y, b4.z, b4.w};
            #pragma unroll
            for (int i = 0; i < 8; i++)
                #pragma unroll
                for (int j = 0; j < 4; j++)
                    acc[i][j] = fmaf(a[i], bb[j], acc[i][j]);
        }
        __syncthreads();
    }

    const int n = n0 + tx*4;
    float4 p2v = make_float4(0,0,0,0);
    if (n + 3 < NPROTO) p2v = *(const float4*)&g_p2[n];

    #pragma unroll
    for (int i = 0; i < 8; i++) {
        int m = m0 + ty*8 + i;
        if (m >= NPIX) continue;
        int b = m / SP, s = m - b*SP;
        float f2 = g_f2[m];
        if (n + 3 < NPROTO) {
            float4 o;
            o.x = sqrtf(fmaxf(f2 + p2v.x - 2.0f*acc[i][0], 0.0f) + 1e-12f);
            o.y = sqrtf(fmaxf(f2 + p2v.y - 2.0f*acc[i][1], 0.0f) + 1e-12f);
            o.z = sqrtf(fmaxf(f2 + p2v.z - 2.0f*acc[i][2], 0.0f) + 1e-12f);
            o.w = sqrtf(fmaxf(f2 + p2v.w - 2.0f*acc[i][3], 0.0f) + 1e-12f);
            *(float4*)&g_dist[(s*BATCH + b)*NPROTO + n] = o;
        } else {
            #pragma unroll
            for (int j = 0; j < 4; j++) {
                if (n + j >= NPROTO) continue;
                float d2 = fmaxf(f2 + g_p2[n+j] - 2.0f*acc[i][j], 0.0f);
                g_dist[(s*BATCH + b)*NPROTO + n + j] = sqrtf(d2 + 1e-12f);
            }
        }
    }
}

// ---------------- bilinear x16 upsample + min + act + logits atomics ----------------
__device__ __forceinline__ void bil_coef(int o, int lim, int& ia, int& ib, float& w) {
    int r = o & 15, q = o >> 4;
    int i0;
    if (r >= 8) { i0 = q;     w = (float)(r - 8) * 0.0625f + 0.03125f; }
    else        { i0 = q - 1; w = (float)(r + 8) * 0.0625f + 0.03125f; }
    ia = i0 < 0 ? 0 : i0;
    ib = (i0 + 1 > lim) ? lim : i0 + 1;
}

__global__ void upsample_kernel(float* __restrict__ up, float* __restrict__ out_min,
                                const float* __restrict__ last_w,
                                float* __restrict__ out_logits) {
    const int bp = blockIdx.x;                 // b*NPROTO + p
    const int t = threadIdx.x;                 // 256
    __shared__ float src[SP];
    __shared__ __align__(16) float hrow[HH][IMG];   // 12.25 KB
    __shared__ float red[256];
    __shared__ float s_act;

    const int b = bp / NPROTO, p = bp - b*NPROTO;
    if (t < SP) src[t] = g_dist[(t*BATCH + b)*NPROTO + p];
    __syncthreads();

    // horizontal interpolation: 14 rows x 224
    for (int i = t; i < HH*IMG; i += 256) {
        int row = i / IMG, x = i - row*IMG;
        int xa, xb; float w;
        bil_coef(x, WW - 1, xa, xb, w);
        hrow[row][x] = (1.0f - w)*src[row*WW + xa] + w*src[row*WW + xb];
    }
    __syncthreads();

    float mn = INFINITY;
    float* dst = up + (size_t)bp * UPSZ;
    for (int v = t; v < IMG*UPF4; v += 256) {
        int y = v / UPF4, xv = (v - y*UPF4) * 4;
        int ya, yb; float w;
        bil_coef(y, HH - 1, ya, yb, w);
        float4 A = *(const float4*)&hrow[ya][xv];
        float4 B = *(const float4*)&hrow[yb][xv];
        float4 o;
        float wi = 1.0f - w;
        o.x = wi*A.x + w*B.x;
        o.y = wi*A.y + w*B.y;
        o.z = wi*A.z + w*B.z;
        o.w = wi*A.w + w*B.w;
        mn = fminf(mn, fminf(fminf(o.x, o.y), fminf(o.z, o.w)));
        __stcs((float4*)&dst[(size_t)v*4], o);
    }

    red[t] = mn;
    __syncthreads();
    #pragma unroll
    for (int off = 128; off > 0; off >>= 1) {
        if (t < off) red[t] = fminf(red[t], red[t + off]);
        __syncthreads();
    }
    if (t == 0) {
        float m = red[0];
        out_min[bp] = m;
        s_act = logf((m + 1.0f) / (m + 1e-4f));
    }
    __syncthreads();

    // scatter logits contribution: logits[b][cls] += act * last_w[cls][p]
    if (t < NCLS) {
        float contrib = s_act * __ldg(&last_w[t*NPROTO + p]);
        atomicAdd(&out_logits[b*NCLS + t], contrib);
    }
}

// ---------------- launch ----------------
extern "C" void kernel_launch(void* const* d_in, const int* in_sizes, int n_in,
                              void* d_out, int out_size) {
    const float* fmap   = (const float*)d_in[0];
    const float* w1     = (const float*)d_in[1];
    const float* b1     = (const float*)d_in[2];
    const float* w2     = (const float*)d_in[3];
    const float* b2     = (const float*)d_in[4];
    const float* protos = (const float*)d_in[5];
    const float* last_w = (const float*)d_in[6];

    float* out        = (float*)d_out;
    float* out_logits = out;                               // 4*200
    float* out_min    = out + BATCH*NCLS;                  // 4*2000
    float* out_up     = out + BATCH*NCLS + BATCH*NPROTO;   // 4*2000*224*224

    float* gx; cudaGetSymbolAddress((void**)&gx, g_x);
    float* gh; cudaGetSymbolAddress((void**)&gh, g_h);
    float* gf; cudaGetSymbolAddress((void**)&gf, g_f);

    const int p2_blocks = (NPROTO + 3)/4;                  // 500
    prep0_kernel<<<TR_BLOCKS + p2_blocks, 128>>>(fmap, protos, out_logits);
    dim3 ggrid(CCH/BN, (NPIX + BM - 1)/BM);                // (2, 13)
    addon_gemm_kernel<1><<<ggrid, 256>>>(gx, w1, b1, gh);
    addon_gemm_kernel<2><<<ggrid, 256>>>(gh, w2, b2, gf);
    dist_kernel<<<dim3((NPROTO + DBN - 1)/DBN, (NPIX + DBM - 1)/DBM), 256>>>(protos);
    upsample_kernel<<<BATCH*NPROTO, 256>>>(out_up, out_min, last_w, out_logits);
}

// round 8
// speedup vs baseline: 1.6181x; 1.0009x over previous
#include <cuda_runtime.h>
#include <math.h>

#define BATCH   4
#define CCH     128
#define HH      14
#define WW      14
#define SP      (HH*WW)        // 196
#define NPIX    (BATCH*SP)     // 784
#define NPROTO  2000
#define NCLS    200
#define IMG     224
#define UPF4    (IMG/4)        // 56
#define UPSZ    (IMG*IMG)      // 50176

// ---------------- scratch ----------------
__device__ __align__(16) float g_x[NPIX*CCH];       // transposed fmap, pixel-major
__device__ __align__(16) float g_h[NPIX*CCH];       // relu(layer1), pixel-major
__device__ __align__(16) float g_f[NPIX*CCH];       // sigmoid features, pixel-major
__device__ __align__(16) float g_f2[NPIX];
__device__ __align__(16) float g_p2[NPROTO];
// dist layout: [s][b][n]  ->  index (s*BATCH + b)*NPROTO + n   (coalesced dist stores)
__device__ __align__(16) float g_dist[SP*BATCH*NPROTO];

// ---------------- kernel 0: transpose fmap -> pixel-major, p2, zero accumulators ----
#define TR_BLOCKS (BATCH*4*7)   // 4 c-tiles x 7 s-tiles per batch = 112
__global__ void prep0_kernel(const float* __restrict__ fmap,
                             const float* __restrict__ protos,
                             float* __restrict__ out_logits) {
    const int t = threadIdx.x;   // 128
    if (blockIdx.x == 0) {
        for (int i = t; i < BATCH*NCLS; i += 128) out_logits[i] = 0.0f;
        for (int i = t; i < NPIX; i += 128) g_f2[i] = 0.0f;
    }
    if (blockIdx.x >= TR_BLOCKS) {
        // ---- ||p||^2: 4 protos per block, 32 lanes each ----
        int p = (blockIdx.x - TR_BLOCKS) * 4 + (t >> 5);
        int lane = t & 31;
        if (p >= NPROTO) return;
        float s = 0.0f;
        #pragma unroll
        for (int c = lane; c < CCH; c += 32) {
            float v = protos[p*CCH + c];
            s = fmaf(v, v, s);
        }
        #pragma unroll
        for (int o = 16; o > 0; o >>= 1) s += __shfl_xor_sync(0xFFFFFFFFu, s, o);
        if (lane == 0) g_p2[p] = s;
        return;
    }

    // ---- 32x32 tile transpose: fmap[b][c][s] -> g_x[b*SP+s][c] ----
    const int tb = blockIdx.x;
    const int b  = tb / 28;
    const int rem = tb - b*28;
    const int tc = rem / 7;           // c-tile 0..3
    const int ts = rem - tc*7;        // s-tile 0..6
    const int tx = t & 31;
    const int ty = t >> 5;            // 0..3

    __shared__ float sm[32][33];

    #pragma unroll
    for (int r = 0; r < 8; r++) {
        int c_local = ty*8 + r;
        int s = ts*32 + tx;
        if (s < SP)
            sm[c_local][tx] = fmap[(b*CCH + tc*32 + c_local)*SP + s];
    }
    __syncthreads();
    #pragma unroll
    for (int r = 0; r < 8; r++) {
        int s_local = ty*8 + r;
        int s = ts*32 + s_local;
        if (s < SP)
            g_x[(b*SP + s)*CCH + tc*32 + tx] = sm[tx][s_local];
    }
}

// ---------------- addon gemms: 64x64 tile, 4x4 micro ----------------
#define BM 64
#define BN 64
#define BK 32

// addon gemm: out[m][n] = act( sum_k A[m][k]*W[n][k] + bias[n] )
// LAYER = 1: relu -> g_h ; LAYER = 2: sigmoid -> g_f + f2 atomics
template<int LAYER>
__global__ void addon_gemm_kernel(const float* __restrict__ A,
                                  const float* __restrict__ W,
                                  const float* __restrict__ bias,
                                  float* __restrict__ out) {
    __shared__ float As[BK][BM + 4];
    __shared__ float Bs[BK][BN + 4];
    const int tid = threadIdx.x;        // 256
    const int tx = tid & 15, ty = tid >> 4;
    const int m0 = blockIdx.y * BM;
    const int n0 = blockIdx.x * BN;

    float acc[4][4] = {};

    for (int k0 = 0; k0 < CCH; k0 += BK) {
        #pragma unroll
        for (int l = 0; l < 2; l++) {
            int idx = tid + l*256;
            int row = idx >> 3;
            int kc4 = idx & 7;
            float4 v = make_float4(0,0,0,0);
            int m = m0 + row;
            if (m < NPIX) v = *(const float4*)&A[m*CCH + k0 + kc4*4];
            As[kc4*4+0][row] = v.x; As[kc4*4+1][row] = v.y;
            As[kc4*4+2][row] = v.z; As[kc4*4+3][row] = v.w;
            int n = n0 + row;
            float4 u = *(const float4*)&W[n*CCH + k0 + kc4*4];
            Bs[kc4*4+0][row] = u.x; Bs[kc4*4+1][row] = u.y;
            Bs[kc4*4+2][row] = u.z; Bs[kc4*4+3][row] = u.w;
        }
        __syncthreads();
        #pragma unroll
        for (int k = 0; k < BK; k++) {
            float4 a4 = *(const float4*)&As[k][ty*4];
            float4 b4 = *(const float4*)&Bs[k][tx*4];
            float a[4] = {a4.x, a4.y, a4.z, a4.w};
            float bb[4] = {b4.x, b4.y, b4.z, b4.w};
            #pragma unroll
            for (int i = 0; i < 4; i++)
                #pragma unroll
                for (int j = 0; j < 4; j++)
                    acc[i][j] = fmaf(a[i], bb[j], acc[i][j]);
        }
        __syncthreads();
    }

    float bs[4];
    #pragma unroll
    for (int j = 0; j < 4; j++) bs[j] = bias[n0 + tx*4 + j];

    #pragma unroll
    for (int i = 0; i < 4; i++) {
        int m = m0 + ty*4 + i;
        bool valid = (m < NPIX);
        float f2p = 0.0f;
        #pragma unroll
        for (int j = 0; j < 4; j++) {
            float v = acc[i][j] + bs[j];
            if (LAYER == 1) {
                v = fmaxf(v, 0.0f);
            } else {
                v = 1.0f / (1.0f + __expf(-v));
                f2p = fmaf(v, v, f2p);
            }
            if (valid) out[m*CCH + n0 + tx*4 + j] = v;
        }
        if (LAYER == 2) {
            #pragma unroll
            for (int o = 8; o > 0; o >>= 1)
                f2p += __shfl_xor_sync(0xFFFFFFFFu, f2p, o);
            if (tx == 0 && valid) atomicAdd(&g_f2[m], f2p);
        }
    }
}

// ---------------- distance GEMM: 64x64 tile, 4x4 micro, coalesced stores ----------------
__global__ void dist_kernel(const float* __restrict__ protos) {
    __shared__ float As[BK][BM + 4];
    __shared__ float Bs[BK][BN + 4];
    const int tid = threadIdx.x;        // 256
    const int tx = tid & 15, ty = tid >> 4;
    const int m0 = blockIdx.y * BM;
    const int n0 = blockIdx.x * BN;

    float acc[4][4] = {};

    for (int k0 = 0; k0 < CCH; k0 += BK) {
        #pragma unroll
        for (int l = 0; l < 2; l++) {
            int idx = tid + l*256;
            int row = idx >> 3;
            int kc4 = idx & 7;
            float4 v = make_float4(0,0,0,0);
            int m = m0 + row;
            if (m < NPIX) v = *(const float4*)&g_f[m*CCH + k0 + kc4*4];
            As[kc4*4+0][row] = v.x; As[kc4*4+1][row] = v.y;
            As[kc4*4+2][row] = v.z; As[kc4*4+3][row] = v.w;
            float4 u = make_float4(0,0,0,0);
            int n = n0 + row;
            if (n < NPROTO) u = *(const float4*)&protos[n*CCH + k0 + kc4*4];
            Bs[kc4*4+0][row] = u.x; Bs[kc4*4+1][row] = u.y;
            Bs[kc4*4+2][row] = u.z; Bs[kc4*4+3][row] = u.w;
        }
        __syncthreads();
        #pragma unroll
        for (int k = 0; k < BK; k++) {
            float4 a4 = *(const float4*)&As[k][ty*4];
            float4 b4 = *(const float4*)&Bs[k][tx*4];
            float a[4] = {a4.x, a4.y, a4.z, a4.w};
            float bb[4] = {b4.x, b4.y, b4.z, b4.w};
            #pragma unroll
            for (int i = 0; i < 4; i++)
                #pragma unroll
                for (int j = 0; j < 4; j++)
                    acc[i][j] = fmaf(a[i], bb[j], acc[i][j]);
        }
        __syncthreads();
    }

    const int n = n0 + tx*4;
    float4 p2v = make_float4(0,0,0,0);
    if (n + 3 < NPROTO) p2v = *(const float4*)&g_p2[n];

    #pragma unroll
    for (int i = 0; i < 4; i++) {
        int m = m0 + ty*4 + i;
        if (m >= NPIX) continue;
        int b = m / SP, s = m - b*SP;
        float f2 = g_f2[m];
        if (n + 3 < NPROTO) {
            float4 o;
            o.x = sqrtf(fmaxf(f2 + p2v.x - 2.0f*acc[i][0], 0.0f) + 1e-12f);
            o.y = sqrtf(fmaxf(f2 + p2v.y - 2.0f*acc[i][1], 0.0f) + 1e-12f);
            o.z = sqrtf(fmaxf(f2 + p2v.z - 2.0f*acc[i][2], 0.0f) + 1e-12f);
            o.w = sqrtf(fmaxf(f2 + p2v.w - 2.0f*acc[i][3], 0.0f) + 1e-12f);
            *(float4*)&g_dist[(s*BATCH + b)*NPROTO + n] = o;
        } else {
            #pragma unroll
            for (int j = 0; j < 4; j++) {
                if (n + j >= NPROTO) continue;
                float d2 = fmaxf(f2 + g_p2[n+j] - 2.0f*acc[i][j], 0.0f);
                g_dist[(s*BATCH + b)*NPROTO + n + j] = sqrtf(d2 + 1e-12f);
            }
        }
    }
}

// ---------------- bilinear x16 upsample + min + act + logits atomics ----------------
__device__ __forceinline__ void bil_coef(int o, int lim, int& ia, int& ib, float& w) {
    int r = o & 15, q = o >> 4;
    int i0;
    if (r >= 8) { i0 = q;     w = (float)(r - 8) * 0.0625f + 0.03125f; }
    else        { i0 = q - 1; w = (float)(r + 8) * 0.0625f + 0.03125f; }
    ia = i0 < 0 ? 0 : i0;
    ib = (i0 + 1 > lim) ? lim : i0 + 1;
}

__global__ void upsample_kernel(float* __restrict__ up, float* __restrict__ out_min,
                                const float* __restrict__ last_w,
                                float* __restrict__ out_logits) {
    const int bp = blockIdx.x;                 // b*NPROTO + p
    const int t = threadIdx.x;                 // 256
    __shared__ float src[SP];
    __shared__ __align__(16) float hrow[HH][IMG];   // 12.25 KB
    __shared__ float red[256];
    __shared__ float s_act;

    const int b = bp / NPROTO, p = bp - b*NPROTO;
    if (t < SP) src[t] = g_dist[(t*BATCH + b)*NPROTO + p];
    __syncthreads();

    // horizontal interpolation: 14 rows x 224
    for (int i = t; i < HH*IMG; i += 256) {
        int row = i / IMG, x = i - row*IMG;
        int xa, xb; float w;
        bil_coef(x, WW - 1, xa, xb, w);
        hrow[row][x] = (1.0f - w)*src[row*WW + xa] + w*src[row*WW + xb];
    }
    __syncthreads();

    float mn = INFINITY;
    float* dst = up + (size_t)bp * UPSZ;
    for (int v = t; v < IMG*UPF4; v += 256) {
        int y = v / UPF4, xv = (v - y*UPF4) * 4;
        int ya, yb; float w;
        bil_coef(y, HH - 1, ya, yb, w);
        float4 A = *(const float4*)&hrow[ya][xv];
        float4 B = *(const float4*)&hrow[yb][xv];
        float4 o;
        float wi = 1.0f - w;
        o.x = wi*A.x + w*B.x;
        o.y = wi*A.y + w*B.y;
        o.z = wi*A.z + w*B.z;
        o.w = wi*A.w + w*B.w;
        mn = fminf(mn, fminf(fminf(o.x, o.y), fminf(o.z, o.w)));
        __stcs((float4*)&dst[(size_t)v*4], o);
    }

    red[t] = mn;
    __syncthreads();
    #pragma unroll
    for (int off = 128; off > 0; off >>= 1) {
        if (t < off) red[t] = fminf(red[t], red[t + off]);
        __syncthreads();
    }
    if (t == 0) {
        float m = red[0];
        out_min[bp] = m;
        s_act = logf((m + 1.0f) / (m + 1e-4f));
    }
    __syncthreads();

    // scatter logits contribution: logits[b][cls] += act * last_w[cls][p]
    if (t < NCLS) {
        float contrib = s_act * __ldg(&last_w[t*NPROTO + p]);
        atomicAdd(&out_logits[b*NCLS + t], contrib);
    }
}

// ---------------- launch ----------------
extern "C" void kernel_launch(void* const* d_in, const int* in_sizes, int n_in,
                              void* d_out, int out_size) {
    const float* fmap   = (const float*)d_in[0];
    const float* w1     = (const float*)d_in[1];
    const float* b1     = (const float*)d_in[2];
    const float* w2     = (const float*)d_in[3];
    const float* b2     = (const float*)d_in[4];
    const float* protos = (const float*)d_in[5];
    const float* last_w = (const float*)d_in[6];

    float* out        = (float*)d_out;
    float* out_logits = out;                               // 4*200
    float* out_min    = out + BATCH*NCLS;                  // 4*2000
    float* out_up     = out + BATCH*NCLS + BATCH*NPROTO;   // 4*2000*224*224

    float* gx; cudaGetSymbolAddress((void**)&gx, g_x);
    float* gh; cudaGetSymbolAddress((void**)&gh, g_h);
    float* gf; cudaGetSymbolAddress((void**)&gf, g_f);

    const int p2_blocks = (NPROTO + 3)/4;                  // 500
    prep0_kernel<<<TR_BLOCKS + p2_blocks, 128>>>(fmap, protos, out_logits);
    dim3 ggrid(CCH/BN, (NPIX + BM - 1)/BM);                // (2, 13)
    addon_gemm_kernel<1><<<ggrid, 256>>>(gx, w1, b1, gh);
    addon_gemm_kernel<2><<<ggrid, 256>>>(gh, w2, b2, gf);
    dist_kernel<<<dim3((NPROTO + BN - 1)/BN, (NPIX + BM - 1)/BM), 256>>>(protos);
    upsample_kernel<<<BATCH*NPROTO, 256>>>(out_up, out_min, last_w, out_logits);
}

// round 9
// speedup vs baseline: 1.6200x; 1.0012x over previous
#include <cuda_runtime.h>
#include <math.h>

#define BATCH   4
#define CCH     128
#define HH      14
#define WW      14
#define SP      (HH*WW)        // 196
#define NPIX    (BATCH*SP)     // 784
#define NPROTO  2000
#define NCLS    200
#define IMG     224
#define UPF4    (IMG/4)        // 56
#define UPSZ    (IMG*IMG)      // 50176

// ---------------- scratch ----------------
__device__ __align__(16) float g_x[NPIX*CCH];       // transposed fmap, pixel-major
__device__ __align__(16) float g_h[NPIX*CCH];       // relu(layer1), pixel-major
__device__ __align__(16) float g_f[NPIX*CCH];       // sigmoid features, pixel-major
__device__ __align__(16) float g_f2[NPIX];
__device__ __align__(16) float g_p2[NPROTO];
// dist layout: [s][b][n]  ->  index (s*BATCH + b)*NPROTO + n   (coalesced dist stores)
__device__ __align__(16) float g_dist[SP*BATCH*NPROTO];

// ---------------- kernel 0: transpose fmap -> pixel-major, p2, zero accumulators ----
#define TR_BLOCKS (BATCH*4*7)   // 4 c-tiles x 7 s-tiles per batch = 112
__global__ void prep0_kernel(const float* __restrict__ fmap,
                             const float* __restrict__ protos,
                             float* __restrict__ out_logits) {
    const int t = threadIdx.x;   // 128
    if (blockIdx.x == 0) {
        for (int i = t; i < BATCH*NCLS; i += 128) out_logits[i] = 0.0f;
        for (int i = t; i < NPIX; i += 128) g_f2[i] = 0.0f;
    }
    if (blockIdx.x >= TR_BLOCKS) {
        // ---- ||p||^2: 4 protos per block, 32 lanes each ----
        int p = (blockIdx.x - TR_BLOCKS) * 4 + (t >> 5);
        int lane = t & 31;
        if (p >= NPROTO) return;
        float s = 0.0f;
        #pragma unroll
        for (int c = lane; c < CCH; c += 32) {
            float v = protos[p*CCH + c];
            s = fmaf(v, v, s);
        }
        #pragma unroll
        for (int o = 16; o > 0; o >>= 1) s += __shfl_xor_sync(0xFFFFFFFFu, s, o);
        if (lane == 0) g_p2[p] = s;
        return;
    }

    // ---- 32x32 tile transpose: fmap[b][c][s] -> g_x[b*SP+s][c] ----
    const int tb = blockIdx.x;
    const int b  = tb / 28;
    const int rem = tb - b*28;
    const int tc = rem / 7;           // c-tile 0..3
    const int ts = rem - tc*7;        // s-tile 0..6
    const int tx = t & 31;
    const int ty = t >> 5;            // 0..3

    __shared__ float sm[32][33];

    #pragma unroll
    for (int r = 0; r < 8; r++) {
        int c_local = ty*8 + r;
        int s = ts*32 + tx;
        if (s < SP)
            sm[c_local][tx] = fmap[(b*CCH + tc*32 + c_local)*SP + s];
    }
    __syncthreads();
    #pragma unroll
    for (int r = 0; r < 8; r++) {
        int s_local = ty*8 + r;
        int s = ts*32 + s_local;
        if (s < SP)
            g_x[(b*SP + s)*CCH + tc*32 + tx] = sm[tx][s_local];
    }
}

// ---------------- addon gemms: 64x64 tile, 4x4 micro ----------------
#define BM 64
#define BN 64
#define BK 32

// addon gemm: out[m][n] = act( sum_k A[m][k]*W[n][k] + bias[n] )
// LAYER = 1: relu -> g_h ; LAYER = 2: sigmoid -> g_f + f2 atomics
template<int LAYER>
__global__ void addon_gemm_kernel(const float* __restrict__ A,
                                  const float* __restrict__ W,
                                  const float* __restrict__ bias,
                                  float* __restrict__ out) {
    __shared__ float As[BK][BM + 4];
    __shared__ float Bs[BK][BN + 4];
    const int tid = threadIdx.x;        // 256
    const int tx = tid & 15, ty = tid >> 4;
    const int m0 = blockIdx.y * BM;
    const int n0 = blockIdx.x * BN;

    float acc[4][4] = {};

    for (int k0 = 0; k0 < CCH; k0 += BK) {
        #pragma unroll
        for (int l = 0; l < 2; l++) {
            int idx = tid + l*256;
            int row = idx >> 3;
            int kc4 = idx & 7;
            float4 v = make_float4(0,0,0,0);
            int m = m0 + row;
            if (m < NPIX) v = *(const float4*)&A[m*CCH + k0 + kc4*4];
            As[kc4*4+0][row] = v.x; As[kc4*4+1][row] = v.y;
            As[kc4*4+2][row] = v.z; As[kc4*4+3][row] = v.w;
            int n = n0 + row;
            float4 u = *(const float4*)&W[n*CCH + k0 + kc4*4];
            Bs[kc4*4+0][row] = u.x; Bs[kc4*4+1][row] = u.y;
            Bs[kc4*4+2][row] = u.z; Bs[kc4*4+3][row] = u.w;
        }
        __syncthreads();
        #pragma unroll
        for (int k = 0; k < BK; k++) {
            float4 a4 = *(const float4*)&As[k][ty*4];
            float4 b4 = *(const float4*)&Bs[k][tx*4];
            float a[4] = {a4.x, a4.y, a4.z, a4.w};
            float bb[4] = {b4.x, b4.y, b4.z, b4.w};
            #pragma unroll
            for (int i = 0; i < 4; i++)
                #pragma unroll
                for (int j = 0; j < 4; j++)
                    acc[i][j] = fmaf(a[i], bb[j], acc[i][j]);
        }
        __syncthreads();
    }

    float bs[4];
    #pragma unroll
    for (int j = 0; j < 4; j++) bs[j] = bias[n0 + tx*4 + j];

    #pragma unroll
    for (int i = 0; i < 4; i++) {
        int m = m0 + ty*4 + i;
        bool valid = (m < NPIX);
        float f2p = 0.0f;
        #pragma unroll
        for (int j = 0; j < 4; j++) {
            float v = acc[i][j] + bs[j];
            if (LAYER == 1) {
                v = fmaxf(v, 0.0f);
            } else {
                v = 1.0f / (1.0f + __expf(-v));
                f2p = fmaf(v, v, f2p);
            }
            if (valid) out[m*CCH + n0 + tx*4 + j] = v;
        }
        if (LAYER == 2) {
            #pragma unroll
            for (int o = 8; o > 0; o >>= 1)
                f2p += __shfl_xor_sync(0xFFFFFFFFu, f2p, o);
            if (tx == 0 && valid) atomicAdd(&g_f2[m], f2p);
        }
    }
}

// ---------------- distance GEMM: 64x32 tile, 128 threads, 4x4 micro ----------------
#define DBM 64
#define DBN 32
#define DBK 32
__global__ void __launch_bounds__(128) dist_kernel(const float* __restrict__ protos) {
    __shared__ float As[DBK][DBM + 4];
    __shared__ float Bs[DBK][DBN + 4];
    const int tid = threadIdx.x;        // 128
    const int tx = tid & 7, ty = tid >> 3;   // tx: 0..7 (n), ty: 0..15 (m)
    const int m0 = blockIdx.y * DBM;
    const int n0 = blockIdx.x * DBN;

    float acc[4][4] = {};

    for (int k0 = 0; k0 < CCH; k0 += DBK) {
        // A: 64 rows x 8 float4 = 512 float4 -> 4 per thread
        #pragma unroll
        for (int l = 0; l < 4; l++) {
            int idx = tid + l*128;
            int row = idx >> 3;
            int kc4 = idx & 7;
            float4 v = make_float4(0,0,0,0);
            int m = m0 + row;
            if (m < NPIX) v = *(const float4*)&g_f[m*CCH + k0 + kc4*4];
            As[kc4*4+0][row] = v.x; As[kc4*4+1][row] = v.y;
            As[kc4*4+2][row] = v.z; As[kc4*4+3][row] = v.w;
        }
        // B: 32 rows x 8 float4 = 256 float4 -> 2 per thread
        #pragma unroll
        for (int l = 0; l < 2; l++) {
            int idx = tid + l*128;
            int row = idx >> 3;
            int kc4 = idx & 7;
            float4 u = make_float4(0,0,0,0);
            int n = n0 + row;
            if (n < NPROTO) u = *(const float4*)&protos[n*CCH + k0 + kc4*4];
            Bs[kc4*4+0][row] = u.x; Bs[kc4*4+1][row] = u.y;
            Bs[kc4*4+2][row] = u.z; Bs[kc4*4+3][row] = u.w;
        }
        __syncthreads();
        #pragma unroll
        for (int k = 0; k < DBK; k++) {
            float4 a4 = *(const float4*)&As[k][ty*4];
            float4 b4 = *(const float4*)&Bs[k][tx*4];
            float a[4] = {a4.x, a4.y, a4.z, a4.w};
            float bb[4] = {b4.x, b4.y, b4.z, b4.w};
            #pragma unroll
            for (int i = 0; i < 4; i++)
                #pragma unroll
                for (int j = 0; j < 4; j++)
                    acc[i][j] = fmaf(a[i], bb[j], acc[i][j]);
        }
        __syncthreads();
    }

    const int n = n0 + tx*4;
    float4 p2v = make_float4(0,0,0,0);
    if (n + 3 < NPROTO) p2v = *(const float4*)&g_p2[n];

    #pragma unroll
    for (int i = 0; i < 4; i++) {
        int m = m0 + ty*4 + i;
        if (m >= NPIX) continue;
        int b = m / SP, s = m - b*SP;
        float f2 = g_f2[m];
        if (n + 3 < NPROTO) {
            float4 o;
            o.x = sqrtf(fmaxf(f2 + p2v.x - 2.0f*acc[i][0], 0.0f) + 1e-12f);
            o.y = sqrtf(fmaxf(f2 + p2v.y - 2.0f*acc[i][1], 0.0f) + 1e-12f);
            o.z = sqrtf(fmaxf(f2 + p2v.z - 2.0f*acc[i][2], 0.0f) + 1e-12f);
            o.w = sqrtf(fmaxf(f2 + p2v.w - 2.0f*acc[i][3], 0.0f) + 1e-12f);
            *(float4*)&g_dist[(s*BATCH + b)*NPROTO + n] = o;
        } else {
            #pragma unroll
            for (int j = 0; j < 4; j++) {
                if (n + j >= NPROTO) continue;
                float d2 = fmaxf(f2 + g_p2[n+j] - 2.0f*acc[i][j], 0.0f);
                g_dist[(s*BATCH + b)*NPROTO + n + j] = sqrtf(d2 + 1e-12f);
            }
        }
    }
}

// ---------------- bilinear x16 upsample + min + act + logits atomics ----------------
__device__ __forceinline__ void bil_coef(int o, int lim, int& ia, int& ib, float& w) {
    int r = o & 15, q = o >> 4;
    int i0;
    if (r >= 8) { i0 = q;     w = (float)(r - 8) * 0.0625f + 0.03125f; }
    else        { i0 = q - 1; w = (float)(r + 8) * 0.0625f + 0.03125f; }
    ia = i0 < 0 ? 0 : i0;
    ib = (i0 + 1 > lim) ? lim : i0 + 1;
}

__global__ void upsample_kernel(float* __restrict__ up, float* __restrict__ out_min,
                                const float* __restrict__ last_w,
                                float* __restrict__ out_logits) {
    const int bp = blockIdx.x;                 // b*NPROTO + p
    const int t = threadIdx.x;                 // 256
    __shared__ float src[SP];
    __shared__ __align__(16) float hrow[HH][IMG];   // 12.25 KB
    __shared__ float red[256];
    __shared__ float s_act;

    const int b = bp / NPROTO, p = bp - b*NPROTO;
    if (t < SP) src[t] = g_dist[(t*BATCH + b)*NPROTO + p];
    __syncthreads();

    // horizontal interpolation: 14 rows x 224
    for (int i = t; i < HH*IMG; i += 256) {
        int row = i / IMG, x = i - row*IMG;
        int xa, xb; float w;
        bil_coef(x, WW - 1, xa, xb, w);
        hrow[row][x] = (1.0f - w)*src[row*WW + xa] + w*src[row*WW + xb];
    }
    __syncthreads();

    float mn = INFINITY;
    float* dst = up + (size_t)bp * UPSZ;
    for (int v = t; v < IMG*UPF4; v += 256) {
        int y = v / UPF4, xv = (v - y*UPF4) * 4;
        int ya, yb; float w;
        bil_coef(y, HH - 1, ya, yb, w);
        float4 A = *(const float4*)&hrow[ya][xv];
        float4 B = *(const float4*)&hrow[yb][xv];
        float4 o;
        float wi = 1.0f - w;
        o.x = wi*A.x + w*B.x;
        o.y = wi*A.y + w*B.y;
        o.z = wi*A.z + w*B.z;
        o.w = wi*A.w + w*B.w;
        mn = fminf(mn, fminf(fminf(o.x, o.y), fminf(o.z, o.w)));
        __stcs((float4*)&dst[(size_t)v*4], o);
    }

    red[t] = mn;
    __syncthreads();
    #pragma unroll
    for (int off = 128; off > 0; off >>= 1) {
        if (t < off) red[t] = fminf(red[t], red[t + off]);
        __syncthreads();
    }
    if (t == 0) {
        float m = red[0];
        out_min[bp] = m;
        s_act = logf((m + 1.0f) / (m + 1e-4f));
    }
    __syncthreads();

    // scatter logits contribution: logits[b][cls] += act * last_w[cls][p]
    if (t < NCLS) {
        float contrib = s_act * __ldg(&last_w[t*NPROTO + p]);
        atomicAdd(&out_logits[b*NCLS + t], contrib);
    }
}

// ---------------- launch ----------------
extern "C" void kernel_launch(void* const* d_in, const int* in_sizes, int n_in,
                              void* d_out, int out_size) {
    const float* fmap   = (const float*)d_in[0];
    const float* w1     = (const float*)d_in[1];
    const float* b1     = (const float*)d_in[2];
    const float* w2     = (const float*)d_in[3];
    const float* b2     = (const float*)d_in[4];
    const float* protos = (const float*)d_in[5];
    const float* last_w = (const float*)d_in[6];

    float* out        = (float*)d_out;
    float* out_logits = out;                               // 4*200
    float* out_min    = out + BATCH*NCLS;                  // 4*2000
    float* out_up     = out + BATCH*NCLS + BATCH*NPROTO;   // 4*2000*224*224

    float* gx; cudaGetSymbolAddress((void**)&gx, g_x);
    float* gh; cudaGetSymbolAddress((void**)&gh, g_h);
    float* gf; cudaGetSymbolAddress((void**)&gf, g_f);

    const int p2_blocks = (NPROTO + 3)/4;                  // 500
    prep0_kernel<<<TR_BLOCKS + p2_blocks, 128>>>(fmap, protos, out_logits);
    dim3 ggrid(CCH/BN, (NPIX + BM - 1)/BM);                // (2, 13)
    addon_gemm_kernel<1><<<ggrid, 256>>>(gx, w1, b1, gh);
    addon_gemm_kernel<2><<<ggrid, 256>>>(gh, w2, b2, gf);
    dist_kernel<<<dim3((NPROTO + DBN - 1)/DBN, (NPIX + DBM - 1)/DBM), 128>>>(protos);
    upsample_kernel<<<BATCH*NPROTO, 256>>>(out_up, out_min, last_w, out_logits);
}